// round 3
// baseline (speedup 1.0000x reference)
#include <cuda_runtime.h>
#include <math.h>

#define THREADS 256
#define NPTS 4096
#define ITER (NPTS / THREADS)   // 16
#define BATCH 2
#define INV_TAU 50.0f
#define KEXP 72.13475204444817f   // 1/(TAU*ln2), exp(x/TAU) = exp2(x*KEXP)

#define SMEM_FLOATS (3 * NPTS + 8)
#define SMEM_BYTES (SMEM_FLOATS * sizeof(float))

// accumulators: 0 l1, 1 bce, 2 unc, 3 normal, 4 chamfer_row, 5 chamfer_col,
//               6 S-sum (EMD row), 7 T-sum (EMD col), 8 gp
__device__ float g_acc[12];
// per (batch, target m): x = colmin*KEXP + log2(coefB/Zc), y = 1 + Tc*INV_TAU
__device__ float2 g_colstats[BATCH * NPTS];

__device__ __forceinline__ float warpSum(float v) {
#pragma unroll
    for (int o = 16; o > 0; o >>= 1) v += __shfl_xor_sync(0xffffffffu, v, o);
    return v;
}
__device__ __forceinline__ float warpMin(float v) {
#pragma unroll
    for (int o = 16; o > 0; o >>= 1) v = fminf(v, __shfl_xor_sync(0xffffffffu, v, o));
    return v;
}

__device__ __forceinline__ float blockSum(float v, float* sh) {
    __syncthreads();
    v = warpSum(v);
    int w = threadIdx.x >> 5, l = threadIdx.x & 31;
    if (l == 0) sh[w] = v;
    __syncthreads();
    if (threadIdx.x == 0) {
        float x = 0.f;
#pragma unroll
        for (int i = 0; i < THREADS / 32; i++) x += sh[i];
        sh[0] = x;
    }
    __syncthreads();
    return sh[0];
}
__device__ __forceinline__ float blockMin(float v, float* sh) {
    __syncthreads();
    v = warpMin(v);
    int w = threadIdx.x >> 5, l = threadIdx.x & 31;
    if (l == 0) sh[w] = v;
    __syncthreads();
    if (threadIdx.x == 0) {
        float x = sh[0];
#pragma unroll
        for (int i = 1; i < THREADS / 32; i++) x = fminf(x, sh[i]);
        sh[0] = x;
    }
    __syncthreads();
    return sh[0];
}

__global__ void zero_kernel() {
    if (threadIdx.x < 12) g_acc[threadIdx.x] = 0.f;
}

// ---------------- pointwise losses over B*P points ----------------
__global__ void pointwise_kernel(const float* __restrict__ sp, const float* __restrict__ st,
                                 const float* __restrict__ un, const float* __restrict__ op,
                                 const float* __restrict__ ot, const float* __restrict__ na_,
                                 const float* __restrict__ nb_, int n) {
    float s_l1 = 0.f, s_bce = 0.f, s_unc = 0.f, s_nrm = 0.f;
    for (int i = blockIdx.x * blockDim.x + threadIdx.x; i < n; i += gridDim.x * blockDim.x) {
        s_l1 += fabsf(sp[i] - st[i]);
        float p = op[i], t = ot[i];
        s_bce -= t * __logf(p) + (1.f - t) * __logf(1.f - p);
        float u = un[i];
        s_unc += u * (1.f - u);
        float ax = na_[3 * i], ay = na_[3 * i + 1], az = na_[3 * i + 2];
        float bx = nb_[3 * i], by = nb_[3 * i + 1], bz = nb_[3 * i + 2];
        float nna = sqrtf(fmaf(ax, ax, fmaf(ay, ay, az * az)));
        float nnb = sqrtf(fmaf(bx, bx, fmaf(by, by, bz * bz)));
        float cs = fmaf(ax, bx, fmaf(ay, by, az * bz)) /
                   (fmaxf(nna, 1e-8f) * fmaxf(nnb, 1e-8f));
        s_nrm += 1.f - cs;
    }
    __shared__ float sh[8];
    float v;
    v = blockSum(s_l1, sh);  if (threadIdx.x == 0) atomicAdd(&g_acc[0], v);
    v = blockSum(s_bce, sh); if (threadIdx.x == 0) atomicAdd(&g_acc[1], v);
    v = blockSum(s_unc, sh); if (threadIdx.x == 0) atomicAdd(&g_acc[2], v);
    v = blockSum(s_nrm, sh); if (threadIdx.x == 0) atomicAdd(&g_acc[3], v);
}

// -------- column stats: block = one TARGET point m; opponents = pred points --------
__global__ void colstats_kernel(const float* __restrict__ tgt, const float* __restrict__ prd) {
    int m = blockIdx.x, b = blockIdx.y;
    extern __shared__ float sm[];
    float* sx = sm;
    float* sy = sm + NPTS;
    float* sz = sm + 2 * NPTS;
    float* red = sm + 3 * NPTS;

    const float* base = prd + (size_t)b * NPTS * 3;
    for (int j = threadIdx.x; j < 3 * NPTS; j += THREADS) {
        int pt = j / 3, c = j - 3 * pt;
        sm[c * NPTS + pt] = base[j];
    }
    const float* a = tgt + ((size_t)b * NPTS + m) * 3;
    float px = a[0], py = a[1], pz = a[2];
    __syncthreads();

    float d[ITER];
    float mn0 = 1e30f, mn1 = 1e30f;
#pragma unroll
    for (int k = 0; k < ITER; k++) {
        int i = threadIdx.x + k * THREADS;
        float dx = px - sx[i], dy = py - sy[i], dz = pz - sz[i];
        float d2 = fmaxf(fmaf(dx, dx, fmaf(dy, dy, dz * dz)), 1e-12f);
        float r = rsqrtf(d2);
        d[k] = d2 * r;
        if (k & 1) mn1 = fminf(mn1, d[k]); else mn0 = fminf(mn0, d[k]);
    }
    float mn = blockMin(fminf(mn0, mn1), red);
    float m1K = mn * KEXP;
    float Z = 0.f, Su = 0.f;
#pragma unroll
    for (int k = 0; k < ITER; k++) {
        float e = exp2f(fmaf(-d[k], KEXP, m1K));
        Z += e;
        Su = fmaf(e, d[k], Su);
    }
    Z = blockSum(Z, red);
    Su = blockSum(Su, red);
    if (threadIdx.x == 0) {
        float T = Su / Z;
        float coefB = 1.f / (float)(BATCH * NPTS);
        g_colstats[b * NPTS + m] = make_float2(m1K + __log2f(coefB / Z),
                                               fmaf(T, INV_TAU, 1.f));
        atomicAdd(&g_acc[5], mn);   // chamfer (min over n)
        atomicAdd(&g_acc[7], T);    // EMD column term
    }
}

// -------- fused row stats + gradient: block = one PRED point n --------
__global__ void rowpass_kernel(const float* __restrict__ prd, const float* __restrict__ tgt) {
    int n = blockIdx.x, b = blockIdx.y;
    extern __shared__ float sm[];
    float* sx = sm;
    float* sy = sm + NPTS;
    float* sz = sm + 2 * NPTS;
    float* red = sm + 3 * NPTS;

    const float* base = tgt + (size_t)b * NPTS * 3;
    for (int j = threadIdx.x; j < 3 * NPTS; j += THREADS) {
        int pt = j / 3, c = j - 3 * pt;
        sm[c * NPTS + pt] = base[j];
    }
    const float* a = prd + ((size_t)b * NPTS + n) * 3;
    float px = a[0], py = a[1], pz = a[2];
    __syncthreads();

    // distance pass: cache d and the UNIT direction vector (no smem re-read later)
    float d[ITER], ux[ITER], uy[ITER], uz[ITER];
    float mn0 = 1e30f, mn1 = 1e30f;
#pragma unroll
    for (int k = 0; k < ITER; k++) {
        int i = threadIdx.x + k * THREADS;
        float dx = px - sx[i], dy = py - sy[i], dz = pz - sz[i];
        float d2 = fmaxf(fmaf(dx, dx, fmaf(dy, dy, dz * dz)), 1e-12f);
        float r = rsqrtf(d2);
        d[k] = d2 * r;
        ux[k] = dx * r;
        uy[k] = dy * r;
        uz[k] = dz * r;
        if (k & 1) mn1 = fminf(mn1, d[k]); else mn0 = fminf(mn0, d[k]);
    }
    float mn = blockMin(fminf(mn0, mn1), red);
    float m1K = mn * KEXP;
    float Z = 0.f, Su = 0.f;
#pragma unroll
    for (int k = 0; k < ITER; k++) {
        float e = exp2f(fmaf(-d[k], KEXP, m1K));
        Z += e;
        Su = fmaf(e, d[k], Su);
    }
    Z = blockSum(Z, red);
    Su = blockSum(Su, red);
    float S = Su / Z;
    float coefA = 1.f / (float)(BATCH * NPTS);
    float rA = m1K + __log2f(coefA / Z);     // fold 1/Z & 1/(B*N) into exponent
    float c1 = fmaf(S, INV_TAU, 1.f);        // 1 + S/tau
    if (threadIdx.x == 0) {
        atomicAdd(&g_acc[4], mn);   // chamfer (min over m)
        atomicAdd(&g_acc[6], S);    // EMD row term
    }

    const float2* __restrict__ cst = g_colstats + b * NPTS;
    float gx = 0.f, gy = 0.f, gz = 0.f;
#pragma unroll
    for (int k = 0; k < ITER; k++) {
        int i = threadIdx.x + k * THREADS;
        float2 cs = __ldg(&cst[i]);
        float dk = d[k];
        float e1 = exp2f(fmaf(-dk, KEXP, rA));     // r_softmax * 1/(B*N)
        float e2 = exp2f(fmaf(-dk, KEXP, cs.x));   // c_softmax * 1/(B*M)
        float dInv = dk * INV_TAU;
        float G = fmaf(e2, cs.y - dInv, e1 * (c1 - dInv));
        gx = fmaf(G, ux[k], gx);
        gy = fmaf(G, uy[k], gy);
        gz = fmaf(G, uz[k], gz);
    }
    gx = blockSum(gx, red);
    gy = blockSum(gy, red);
    gz = blockSum(gz, red);
    if (threadIdx.x == 0) {
        float nrm = sqrtf(fmaf(gx, gx, fmaf(gy, gy, gz * gz)));
        atomicAdd(&g_acc[8], fabsf(nrm - 1.f));
    }
}

// ---------------- finalize ----------------
__global__ void final_kernel(float* __restrict__ out, int bp) {
    float invBP = 1.f / (float)bp;
    float invBN = 1.f / (float)(BATCH * NPTS);
    float l1 = g_acc[0] * invBP;
    float bce = g_acc[1] * invBP;
    float unc = g_acc[2] * invBP;
    float nrm = g_acc[3] * invBP;
    float cham = (g_acc[4] + g_acc[5]) * invBN;
    float emd = (g_acc[6] + g_acc[7]) * invBN;
    float gp = g_acc[8] * invBN;
    float pt = expf(-bce);
    float occ = 0.75f * (1.f - pt) * (1.f - pt) * bce;
    out[0] = l1 + occ + 0.1f * nrm + cham + 0.25f * emd + 0.05f * gp + 0.1f * unc;
}

extern "C" void kernel_launch(void* const* d_in, const int* in_sizes, int n_in,
                              void* d_out, int out_size) {
    const float* sdf_pred   = (const float*)d_in[0];
    const float* sdf_target = (const float*)d_in[1];
    const float* uncertainty = (const float*)d_in[2];
    const float* occ_pred   = (const float*)d_in[3];
    const float* occ_target = (const float*)d_in[4];
    const float* nrm_pred   = (const float*)d_in[5];
    const float* nrm_target = (const float*)d_in[6];
    const float* pc_pred    = (const float*)d_in[7];
    const float* pc_target  = (const float*)d_in[8];
    float* out = (float*)d_out;

    int bp = in_sizes[0];   // B * P = 200000

    cudaFuncSetAttribute(colstats_kernel, cudaFuncAttributeMaxDynamicSharedMemorySize,
                         (int)SMEM_BYTES);
    cudaFuncSetAttribute(rowpass_kernel, cudaFuncAttributeMaxDynamicSharedMemorySize,
                         (int)SMEM_BYTES);

    zero_kernel<<<1, 32>>>();
    pointwise_kernel<<<448, THREADS>>>(sdf_pred, sdf_target, uncertainty,
                                       occ_pred, occ_target, nrm_pred, nrm_target, bp);
    dim3 grid(NPTS, BATCH);
    colstats_kernel<<<grid, THREADS, SMEM_BYTES>>>(pc_target, pc_pred);
    rowpass_kernel<<<grid, THREADS, SMEM_BYTES>>>(pc_pred, pc_target);
    final_kernel<<<1, 1>>>(out, bp);
}

// round 4
// speedup vs baseline: 1.3000x; 1.3000x over previous
#include <cuda_runtime.h>
#include <math.h>

#define THREADS 256
#define NPTS 4096
#define BATCH 2
#define QPB 32                 // queries per block
#define SUBS 8                 // threads per query
#define CHUNK (NPTS / SUBS)    // 512 opponents per thread
#define INV_TAU 50.0f
#define KEXP 72.13475204444817f   // 1/(TAU*ln2): exp(x/TAU) = exp2(x*KEXP)
#define BIAS 32.0f
#define COEF (1.0f / (float)(BATCH * NPTS))

#define TILE_BYTES (3 * NPTS * sizeof(float))            // 49152
#define ROW_SMEM (TILE_BYTES + NPTS * sizeof(float2))    // 49152 + 32768 = 81920

// accumulators: 0 l1, 1 bce, 2 unc, 3 normal, 4 chamfer_row, 5 chamfer_col,
//               6 S-sum (EMD row), 7 T-sum (EMD col), 8 gp
__device__ float g_acc[12];
// per (batch, target m): x = 2^(colminK + log2(coefB/Zc) - BIAS), y = 1 + Tc/tau
__device__ __align__(16) float2 g_colstats[BATCH * NPTS];

__device__ __forceinline__ float warpSum(float v) {
#pragma unroll
    for (int o = 16; o > 0; o >>= 1) v += __shfl_xor_sync(0xffffffffu, v, o);
    return v;
}

__device__ __forceinline__ float blockSum(float v, float* sh) {
    __syncthreads();
    v = warpSum(v);
    int w = threadIdx.x >> 5, l = threadIdx.x & 31;
    if (l == 0) sh[w] = v;
    __syncthreads();
    if (threadIdx.x == 0) {
        float x = 0.f;
#pragma unroll
        for (int i = 0; i < THREADS / 32; i++) x += sh[i];
        sh[0] = x;
    }
    __syncthreads();
    return sh[0];
}

__global__ void zero_kernel() {
    if (threadIdx.x < 12) g_acc[threadIdx.x] = 0.f;
}

// ---------------- pointwise losses over B*P points ----------------
__global__ void pointwise_kernel(const float* __restrict__ sp, const float* __restrict__ st,
                                 const float* __restrict__ un, const float* __restrict__ op,
                                 const float* __restrict__ ot, const float* __restrict__ na_,
                                 const float* __restrict__ nb_, int n) {
    float s_l1 = 0.f, s_bce = 0.f, s_unc = 0.f, s_nrm = 0.f;
    for (int i = blockIdx.x * blockDim.x + threadIdx.x; i < n; i += gridDim.x * blockDim.x) {
        s_l1 += fabsf(sp[i] - st[i]);
        float p = op[i], t = ot[i];
        s_bce -= t * __logf(p) + (1.f - t) * __logf(1.f - p);
        float u = un[i];
        s_unc += u * (1.f - u);
        float ax = na_[3 * i], ay = na_[3 * i + 1], az = na_[3 * i + 2];
        float bx = nb_[3 * i], by = nb_[3 * i + 1], bz = nb_[3 * i + 2];
        float nna = sqrtf(fmaf(ax, ax, fmaf(ay, ay, az * az)));
        float nnb = sqrtf(fmaf(bx, bx, fmaf(by, by, bz * bz)));
        float cs = fmaf(ax, bx, fmaf(ay, by, az * bz)) /
                   (fmaxf(nna, 1e-8f) * fmaxf(nnb, 1e-8f));
        s_nrm += 1.f - cs;
    }
    __shared__ float sh[8];
    float v;
    v = blockSum(s_l1, sh);  if (threadIdx.x == 0) atomicAdd(&g_acc[0], v);
    v = blockSum(s_bce, sh); if (threadIdx.x == 0) atomicAdd(&g_acc[1], v);
    v = blockSum(s_unc, sh); if (threadIdx.x == 0) atomicAdd(&g_acc[2], v);
    v = blockSum(s_nrm, sh); if (threadIdx.x == 0) atomicAdd(&g_acc[3], v);
}

// -------- colstats: 32 target queries per block, online softmax over pred tile --------
__global__ void colstats_kernel(const float* __restrict__ tgt, const float* __restrict__ prd) {
    extern __shared__ float sm[];   // 3*NPTS floats, interleaved xyz
    int t = threadIdx.x;
    int b = blockIdx.y;
    int qloc = t >> 3, sub = t & 7;
    int m = blockIdx.x * QPB + qloc;

    {
        const float4* src = (const float4*)(prd + (size_t)b * NPTS * 3);
        float4* dst = (float4*)sm;
#pragma unroll
        for (int j = 0; j < (3 * NPTS / 4) / THREADS; j++)
            dst[t + j * THREADS] = src[t + j * THREADS];
    }
    const float* q = tgt + ((size_t)b * NPTS + m) * 3;
    float px = q[0], py = q[1], pz = q[2];
    __syncthreads();

    float mn = 1e30f, Z = 0.f, Su = 0.f;
#pragma unroll 4
    for (int j = 0; j < CHUNK; j++) {
        int i = sub + j * SUBS;
        float dx = px - sm[3 * i], dy = py - sm[3 * i + 1], dz = pz - sm[3 * i + 2];
        float d2 = fmaxf(fmaf(dx, dx, fmaf(dy, dy, dz * dz)), 1e-12f);
        float r = rsqrtf(d2);
        float d = d2 * r;
        if (d < mn) {
            float f = exp2f((d - mn) * KEXP);
            Z *= f; Su *= f;
            mn = d;
        }
        float p = exp2f((mn - d) * KEXP);
        Z += p;
        Su = fmaf(p, d, Su);
    }
    // combine 8 subs (lanes 8k..8k+7)
    float mnG = mn;
#pragma unroll
    for (int o = 1; o < 8; o <<= 1) mnG = fminf(mnG, __shfl_xor_sync(0xffffffffu, mnG, o));
    float f = exp2f((mnG - mn) * KEXP);
    Z *= f; Su *= f;
#pragma unroll
    for (int o = 1; o < 8; o <<= 1) {
        Z += __shfl_xor_sync(0xffffffffu, Z, o);
        Su += __shfl_xor_sync(0xffffffffu, Su, o);
    }
    if (sub == 0) {
        float T = Su / Z;
        // q' = 2^(mnG*K - BIAS) * coefB / Z_acc  (linear-domain col softmax scale)
        float qprime = exp2f(fmaf(mnG, KEXP, -BIAS)) * (COEF / Z);
        g_colstats[b * NPTS + m] = make_float2(qprime, fmaf(T, INV_TAU, 1.f));
        atomicAdd(&g_acc[5], mnG);   // chamfer (min over n)
        atomicAdd(&g_acc[7], T);     // EMD column term
    }
}

// -------- rowpass: fused row softmax + full EMD gradient, single sweep --------
__global__ void rowpass_kernel(const float* __restrict__ prd, const float* __restrict__ tgt) {
    extern __shared__ float sm[];               // 3*NPTS floats (target tile)
    float2* sc = (float2*)(sm + 3 * NPTS);      // NPTS float2 (colstats)
    int t = threadIdx.x;
    int b = blockIdx.y;
    int qloc = t >> 3, sub = t & 7;
    int n = blockIdx.x * QPB + qloc;

    {
        const float4* src = (const float4*)(tgt + (size_t)b * NPTS * 3);
        float4* dst = (float4*)sm;
#pragma unroll
        for (int j = 0; j < (3 * NPTS / 4) / THREADS; j++)
            dst[t + j * THREADS] = src[t + j * THREADS];
        const float4* csrc = (const float4*)(g_colstats + b * NPTS);
        float4* cdst = (float4*)sc;
#pragma unroll
        for (int j = 0; j < (NPTS * 2 / 4) / THREADS; j++)
            cdst[t + j * THREADS] = csrc[t + j * THREADS];
    }
    const float* q = prd + ((size_t)b * NPTS + n) * 3;
    float px = q[0], py = q[1], pz = q[2];
    __syncthreads();

    float mn = 1e30f, Z = 0.f, Su = 0.f;
    float v1x = 0.f, v1y = 0.f, v1z = 0.f;   // sum p*u
    float v2x = 0.f, v2y = 0.f, v2z = 0.f;   // sum p*d*u
    float gcx = 0.f, gcy = 0.f, gcz = 0.f;   // col-side grad (biased scale)
#pragma unroll 4
    for (int j = 0; j < CHUNK; j++) {
        int i = sub + j * SUBS;
        float dx = px - sm[3 * i], dy = py - sm[3 * i + 1], dz = pz - sm[3 * i + 2];
        float d2 = fmaxf(fmaf(dx, dx, fmaf(dy, dy, dz * dz)), 1e-12f);
        float r = rsqrtf(d2);
        float d = d2 * r;
        if (d < mn) {
            float f = exp2f((d - mn) * KEXP);
            Z *= f; Su *= f;
            v1x *= f; v1y *= f; v1z *= f;
            v2x *= f; v2y *= f; v2z *= f;
            gcx *= f; gcy *= f; gcz *= f;
            mn = d;
        }
        float p = exp2f((mn - d) * KEXP);
        Z += p;
        float pd = p * d;
        Su += pd;
        float pr = p * r;
        v1x = fmaf(pr, dx, v1x); v1y = fmaf(pr, dy, v1y); v1z = fmaf(pr, dz, v1z);
        float pdr = pd * r;
        v2x = fmaf(pdr, dx, v2x); v2y = fmaf(pdr, dy, v2y); v2z = fmaf(pdr, dz, v2z);
        float2 cs = sc[i];
        float hr = (p * cs.x) * (cs.y - d * INV_TAU) * r;
        gcx = fmaf(hr, dx, gcx); gcy = fmaf(hr, dy, gcy); gcz = fmaf(hr, dz, gcz);
    }
    // combine 8 subs
    float mnG = mn;
#pragma unroll
    for (int o = 1; o < 8; o <<= 1) mnG = fminf(mnG, __shfl_xor_sync(0xffffffffu, mnG, o));
    float f = exp2f((mnG - mn) * KEXP);
    Z *= f; Su *= f;
    v1x *= f; v1y *= f; v1z *= f;
    v2x *= f; v2y *= f; v2z *= f;
    gcx *= f; gcy *= f; gcz *= f;
#pragma unroll
    for (int o = 1; o < 8; o <<= 1) {
        Z += __shfl_xor_sync(0xffffffffu, Z, o);
        Su += __shfl_xor_sync(0xffffffffu, Su, o);
        v1x += __shfl_xor_sync(0xffffffffu, v1x, o);
        v1y += __shfl_xor_sync(0xffffffffu, v1y, o);
        v1z += __shfl_xor_sync(0xffffffffu, v1z, o);
        v2x += __shfl_xor_sync(0xffffffffu, v2x, o);
        v2y += __shfl_xor_sync(0xffffffffu, v2y, o);
        v2z += __shfl_xor_sync(0xffffffffu, v2z, o);
        gcx += __shfl_xor_sync(0xffffffffu, gcx, o);
        gcy += __shfl_xor_sync(0xffffffffu, gcy, o);
        gcz += __shfl_xor_sync(0xffffffffu, gcz, o);
    }
    if (sub == 0) {
        float S = Su / Z;
        float c1 = fmaf(S, INV_TAU, 1.f);
        float rs = COEF / Z;
        float colsc = exp2f(fmaf(-mnG, KEXP, BIAS));   // 2^(BIAS - mnG*K)
        float gx = rs * fmaf(c1, v1x, -INV_TAU * v2x) + colsc * gcx;
        float gy = rs * fmaf(c1, v1y, -INV_TAU * v2y) + colsc * gcy;
        float gz = rs * fmaf(c1, v1z, -INV_TAU * v2z) + colsc * gcz;
        float nrm = sqrtf(fmaf(gx, gx, fmaf(gy, gy, gz * gz)));
        atomicAdd(&g_acc[8], fabsf(nrm - 1.f));
        atomicAdd(&g_acc[4], mnG);   // chamfer (min over m)
        atomicAdd(&g_acc[6], S);     // EMD row term
    }
}

// ---------------- finalize ----------------
__global__ void final_kernel(float* __restrict__ out, int bp) {
    float invBP = 1.f / (float)bp;
    float invBN = 1.f / (float)(BATCH * NPTS);
    float l1 = g_acc[0] * invBP;
    float bce = g_acc[1] * invBP;
    float unc = g_acc[2] * invBP;
    float nrm = g_acc[3] * invBP;
    float cham = (g_acc[4] + g_acc[5]) * invBN;
    float emd = (g_acc[6] + g_acc[7]) * invBN;
    float gp = g_acc[8] * invBN;
    float pt = expf(-bce);
    float occ = 0.75f * (1.f - pt) * (1.f - pt) * bce;
    out[0] = l1 + occ + 0.1f * nrm + cham + 0.25f * emd + 0.05f * gp + 0.1f * unc;
}

extern "C" void kernel_launch(void* const* d_in, const int* in_sizes, int n_in,
                              void* d_out, int out_size) {
    const float* sdf_pred   = (const float*)d_in[0];
    const float* sdf_target = (const float*)d_in[1];
    const float* uncertainty = (const float*)d_in[2];
    const float* occ_pred   = (const float*)d_in[3];
    const float* occ_target = (const float*)d_in[4];
    const float* nrm_pred   = (const float*)d_in[5];
    const float* nrm_target = (const float*)d_in[6];
    const float* pc_pred    = (const float*)d_in[7];
    const float* pc_target  = (const float*)d_in[8];
    float* out = (float*)d_out;

    int bp = in_sizes[0];   // B * P = 200000

    cudaFuncSetAttribute(colstats_kernel, cudaFuncAttributeMaxDynamicSharedMemorySize,
                         (int)TILE_BYTES);
    cudaFuncSetAttribute(rowpass_kernel, cudaFuncAttributeMaxDynamicSharedMemorySize,
                         (int)ROW_SMEM);

    zero_kernel<<<1, 32>>>();
    pointwise_kernel<<<448, THREADS>>>(sdf_pred, sdf_target, uncertainty,
                                       occ_pred, occ_target, nrm_pred, nrm_target, bp);
    dim3 grid(NPTS / QPB, BATCH);   // 128 x 2
    colstats_kernel<<<grid, THREADS, TILE_BYTES>>>(pc_target, pc_pred);
    rowpass_kernel<<<grid, THREADS, ROW_SMEM>>>(pc_pred, pc_target);
    final_kernel<<<1, 1>>>(out, bp);
}

// round 5
// speedup vs baseline: 1.3635x; 1.0489x over previous
#include <cuda_runtime.h>
#include <math.h>

#define THREADS 256
#define NPTS 4096
#define BATCH 2
#define QPB 16                 // queries per block
#define SUBS 16                // threads per query
#define CHUNK (NPTS / SUBS)    // 256 opponents per thread
#define INV_TAU 50.0f
#define KEXP 72.13475204444817f   // 1/(TAU*ln2): exp(x/TAU) = exp2(x*KEXP)
#define BIAS 32.0f
#define COEF (1.0f / (float)(BATCH * NPTS))

#define TILE_BYTES (3 * NPTS * sizeof(float))   // 49152

// accumulators: 0 l1, 1 bce, 2 unc, 3 normal, 4 chamfer_row, 5 chamfer_col,
//               6 S-sum (EMD row), 7 T-sum (EMD col), 8 gp
__device__ float g_acc[12];
// per (batch, target m): x = 2^(colminK - BIAS)*coefB/Zc, y = 1 + Tc/tau
__device__ __align__(16) float2 g_colstats[BATCH * NPTS];

__device__ __forceinline__ float warpSum(float v) {
#pragma unroll
    for (int o = 16; o > 0; o >>= 1) v += __shfl_xor_sync(0xffffffffu, v, o);
    return v;
}

__device__ __forceinline__ float blockSum(float v, float* sh) {
    __syncthreads();
    v = warpSum(v);
    int w = threadIdx.x >> 5, l = threadIdx.x & 31;
    if (l == 0) sh[w] = v;
    __syncthreads();
    if (threadIdx.x == 0) {
        float x = 0.f;
#pragma unroll
        for (int i = 0; i < THREADS / 32; i++) x += sh[i];
        sh[0] = x;
    }
    __syncthreads();
    return sh[0];
}

__global__ void zero_kernel() {
    if (threadIdx.x < 12) g_acc[threadIdx.x] = 0.f;
}

// ---------------- pointwise losses over B*P points ----------------
__global__ void pointwise_kernel(const float* __restrict__ sp, const float* __restrict__ st,
                                 const float* __restrict__ un, const float* __restrict__ op,
                                 const float* __restrict__ ot, const float* __restrict__ na_,
                                 const float* __restrict__ nb_, int n) {
    float s_l1 = 0.f, s_bce = 0.f, s_unc = 0.f, s_nrm = 0.f;
    for (int i = blockIdx.x * blockDim.x + threadIdx.x; i < n; i += gridDim.x * blockDim.x) {
        s_l1 += fabsf(sp[i] - st[i]);
        float p = op[i], t = ot[i];
        s_bce -= t * __logf(p) + (1.f - t) * __logf(1.f - p);
        float u = un[i];
        s_unc += u * (1.f - u);
        float ax = na_[3 * i], ay = na_[3 * i + 1], az = na_[3 * i + 2];
        float bx = nb_[3 * i], by = nb_[3 * i + 1], bz = nb_[3 * i + 2];
        float nna = sqrtf(fmaf(ax, ax, fmaf(ay, ay, az * az)));
        float nnb = sqrtf(fmaf(bx, bx, fmaf(by, by, bz * bz)));
        float cs = fmaf(ax, bx, fmaf(ay, by, az * bz)) /
                   (fmaxf(nna, 1e-8f) * fmaxf(nnb, 1e-8f));
        s_nrm += 1.f - cs;
    }
    __shared__ float sh[8];
    float v;
    v = blockSum(s_l1, sh);  if (threadIdx.x == 0) atomicAdd(&g_acc[0], v);
    v = blockSum(s_bce, sh); if (threadIdx.x == 0) atomicAdd(&g_acc[1], v);
    v = blockSum(s_unc, sh); if (threadIdx.x == 0) atomicAdd(&g_acc[2], v);
    v = blockSum(s_nrm, sh); if (threadIdx.x == 0) atomicAdd(&g_acc[3], v);
}

// -------- colstats: QPB target queries per block, online softmax over pred tile --------
__global__ void colstats_kernel(const float* __restrict__ tgt, const float* __restrict__ prd) {
    extern __shared__ float sm[];   // 3*NPTS floats, interleaved xyz
    int t = threadIdx.x;
    int b = blockIdx.y;
    int qloc = t / SUBS, sub = t % SUBS;
    int m = blockIdx.x * QPB + qloc;

    {
        const float4* src = (const float4*)(prd + (size_t)b * NPTS * 3);
        float4* dst = (float4*)sm;
#pragma unroll
        for (int j = 0; j < (3 * NPTS / 4) / THREADS; j++)
            dst[t + j * THREADS] = src[t + j * THREADS];
    }
    const float* q = tgt + ((size_t)b * NPTS + m) * 3;
    float px = q[0], py = q[1], pz = q[2];
    __syncthreads();

    float mn = 1e30f, Z = 0.f, Su = 0.f;
#pragma unroll 4
    for (int j = 0; j < CHUNK; j++) {
        int i = sub + j * SUBS;
        float dx = px - sm[3 * i], dy = py - sm[3 * i + 1], dz = pz - sm[3 * i + 2];
        float d2 = fmaxf(fmaf(dx, dx, fmaf(dy, dy, dz * dz)), 1e-12f);
        float r = rsqrtf(d2);
        float d = d2 * r;
        if (d < mn) {
            float f = exp2f((d - mn) * KEXP);
            Z *= f; Su *= f;
            mn = d;
        }
        float p = exp2f((mn - d) * KEXP);
        Z += p;
        Su = fmaf(p, d, Su);
    }
    // combine SUBS lanes
    float mnG = mn;
#pragma unroll
    for (int o = 1; o < SUBS; o <<= 1) mnG = fminf(mnG, __shfl_xor_sync(0xffffffffu, mnG, o));
    float f = exp2f((mnG - mn) * KEXP);
    Z *= f; Su *= f;
#pragma unroll
    for (int o = 1; o < SUBS; o <<= 1) {
        Z += __shfl_xor_sync(0xffffffffu, Z, o);
        Su += __shfl_xor_sync(0xffffffffu, Su, o);
    }
    if (sub == 0) {
        float T = Su / Z;
        float qprime = exp2f(fmaf(mnG, KEXP, -BIAS)) * (COEF / Z);
        g_colstats[b * NPTS + m] = make_float2(qprime, fmaf(T, INV_TAU, 1.f));
        atomicAdd(&g_acc[5], mnG);   // chamfer (min over n)
        atomicAdd(&g_acc[7], T);     // EMD column term
    }
}

// -------- rowpass: fused row softmax + full EMD gradient, single sweep --------
__global__ void rowpass_kernel(const float* __restrict__ prd, const float* __restrict__ tgt) {
    extern __shared__ float sm[];               // 3*NPTS floats (target tile)
    int t = threadIdx.x;
    int b = blockIdx.y;
    int qloc = t / SUBS, sub = t % SUBS;
    int n = blockIdx.x * QPB + qloc;

    {
        const float4* src = (const float4*)(tgt + (size_t)b * NPTS * 3);
        float4* dst = (float4*)sm;
#pragma unroll
        for (int j = 0; j < (3 * NPTS / 4) / THREADS; j++)
            dst[t + j * THREADS] = src[t + j * THREADS];
    }
    const float* q = prd + ((size_t)b * NPTS + n) * 3;
    float px = q[0], py = q[1], pz = q[2];
    const float2* __restrict__ cst = g_colstats + b * NPTS;
    __syncthreads();

    float mn = 1e30f, Z = 0.f, Su = 0.f;
    float v1x = 0.f, v1y = 0.f, v1z = 0.f;   // sum p*u
    float v2x = 0.f, v2y = 0.f, v2z = 0.f;   // sum p*d*u
    float gcx = 0.f, gcy = 0.f, gcz = 0.f;   // col-side grad (biased scale)
#pragma unroll 4
    for (int j = 0; j < CHUNK; j++) {
        int i = sub + j * SUBS;
        float dx = px - sm[3 * i], dy = py - sm[3 * i + 1], dz = pz - sm[3 * i + 2];
        float d2 = fmaxf(fmaf(dx, dx, fmaf(dy, dy, dz * dz)), 1e-12f);
        float r = rsqrtf(d2);
        float d = d2 * r;
        if (d < mn) {
            float f = exp2f((d - mn) * KEXP);
            Z *= f; Su *= f;
            v1x *= f; v1y *= f; v1z *= f;
            v2x *= f; v2y *= f; v2z *= f;
            gcx *= f; gcy *= f; gcz *= f;
            mn = d;
        }
        float p = exp2f((mn - d) * KEXP);
        Z += p;
        float pd = p * d;
        Su += pd;
        float pr = p * r;
        v1x = fmaf(pr, dx, v1x); v1y = fmaf(pr, dy, v1y); v1z = fmaf(pr, dz, v1z);
        float pdr = pd * r;
        v2x = fmaf(pdr, dx, v2x); v2y = fmaf(pdr, dy, v2y); v2z = fmaf(pdr, dz, v2z);
        float2 cs = __ldg(&cst[i]);
        float hr = (p * cs.x) * (cs.y - d * INV_TAU) * r;
        gcx = fmaf(hr, dx, gcx); gcy = fmaf(hr, dy, gcy); gcz = fmaf(hr, dz, gcz);
    }
    // combine SUBS lanes
    float mnG = mn;
#pragma unroll
    for (int o = 1; o < SUBS; o <<= 1) mnG = fminf(mnG, __shfl_xor_sync(0xffffffffu, mnG, o));
    float f = exp2f((mnG - mn) * KEXP);
    Z *= f; Su *= f;
    v1x *= f; v1y *= f; v1z *= f;
    v2x *= f; v2y *= f; v2z *= f;
    gcx *= f; gcy *= f; gcz *= f;
#pragma unroll
    for (int o = 1; o < SUBS; o <<= 1) {
        Z += __shfl_xor_sync(0xffffffffu, Z, o);
        Su += __shfl_xor_sync(0xffffffffu, Su, o);
        v1x += __shfl_xor_sync(0xffffffffu, v1x, o);
        v1y += __shfl_xor_sync(0xffffffffu, v1y, o);
        v1z += __shfl_xor_sync(0xffffffffu, v1z, o);
        v2x += __shfl_xor_sync(0xffffffffu, v2x, o);
        v2y += __shfl_xor_sync(0xffffffffu, v2y, o);
        v2z += __shfl_xor_sync(0xffffffffu, v2z, o);
        gcx += __shfl_xor_sync(0xffffffffu, gcx, o);
        gcy += __shfl_xor_sync(0xffffffffu, gcy, o);
        gcz += __shfl_xor_sync(0xffffffffu, gcz, o);
    }
    if (sub == 0) {
        float S = Su / Z;
        float c1 = fmaf(S, INV_TAU, 1.f);
        float rs = COEF / Z;
        float colsc = exp2f(fmaf(-mnG, KEXP, BIAS));   // 2^(BIAS - mnG*K)
        float gx = rs * fmaf(c1, v1x, -INV_TAU * v2x) + colsc * gcx;
        float gy = rs * fmaf(c1, v1y, -INV_TAU * v2y) + colsc * gcy;
        float gz = rs * fmaf(c1, v1z, -INV_TAU * v2z) + colsc * gcz;
        float nrm = sqrtf(fmaf(gx, gx, fmaf(gy, gy, gz * gz)));
        atomicAdd(&g_acc[8], fabsf(nrm - 1.f));
        atomicAdd(&g_acc[4], mnG);   // chamfer (min over m)
        atomicAdd(&g_acc[6], S);     // EMD row term
    }
}

// ---------------- finalize ----------------
__global__ void final_kernel(float* __restrict__ out, int bp) {
    float invBP = 1.f / (float)bp;
    float invBN = 1.f / (float)(BATCH * NPTS);
    float l1 = g_acc[0] * invBP;
    float bce = g_acc[1] * invBP;
    float unc = g_acc[2] * invBP;
    float nrm = g_acc[3] * invBP;
    float cham = (g_acc[4] + g_acc[5]) * invBN;
    float emd = (g_acc[6] + g_acc[7]) * invBN;
    float gp = g_acc[8] * invBN;
    float pt = expf(-bce);
    float occ = 0.75f * (1.f - pt) * (1.f - pt) * bce;
    out[0] = l1 + occ + 0.1f * nrm + cham + 0.25f * emd + 0.05f * gp + 0.1f * unc;
}

extern "C" void kernel_launch(void* const* d_in, const int* in_sizes, int n_in,
                              void* d_out, int out_size) {
    const float* sdf_pred   = (const float*)d_in[0];
    const float* sdf_target = (const float*)d_in[1];
    const float* uncertainty = (const float*)d_in[2];
    const float* occ_pred   = (const float*)d_in[3];
    const float* occ_target = (const float*)d_in[4];
    const float* nrm_pred   = (const float*)d_in[5];
    const float* nrm_target = (const float*)d_in[6];
    const float* pc_pred    = (const float*)d_in[7];
    const float* pc_target  = (const float*)d_in[8];
    float* out = (float*)d_out;

    int bp = in_sizes[0];   // B * P = 200000

    cudaFuncSetAttribute(colstats_kernel, cudaFuncAttributeMaxDynamicSharedMemorySize,
                         (int)TILE_BYTES);
    cudaFuncSetAttribute(rowpass_kernel, cudaFuncAttributeMaxDynamicSharedMemorySize,
                         (int)TILE_BYTES);

    zero_kernel<<<1, 32>>>();
    pointwise_kernel<<<448, THREADS>>>(sdf_pred, sdf_target, uncertainty,
                                       occ_pred, occ_target, nrm_pred, nrm_target, bp);
    dim3 grid(NPTS / QPB, BATCH);   // 256 x 2 = 512 blocks
    colstats_kernel<<<grid, THREADS, TILE_BYTES>>>(pc_target, pc_pred);
    rowpass_kernel<<<grid, THREADS, TILE_BYTES>>>(pc_pred, pc_target);
    final_kernel<<<1, 1>>>(out, bp);
}

// round 8
// speedup vs baseline: 1.5515x; 1.1379x over previous
#include <cuda_runtime.h>
#include <math.h>

#define THREADS 256
#define NPTS 4096
#define BATCH 2
#define QPB 16                 // queries per block
#define SUBS 16                // threads per query
#define CHUNK (NPTS / SUBS)    // 256 opponents per thread
#define INV_TAU 50.0f
#define KEXP 72.13475204444817f   // 1/(TAU*ln2): exp(x/TAU) = exp2(x*KEXP)
#define BIAS 32.0f
#define COEF (1.0f / (float)(BATCH * NPTS))
#define MN_INIT 1e30f

// tile: float2 (x,y) plane [NPTS] + float z plane [NPTS] = 48KB
#define TILE_BYTES (NPTS * sizeof(float2) + NPTS * sizeof(float))

// accumulators: 0 l1, 1 bce, 2 unc, 3 normal, 4 chamfer_row, 5 chamfer_col,
//               6 S-sum (EMD row), 7 T-sum (EMD col), 8 gp
__device__ float g_acc[12];
// per (batch, target m): x = 2^(colminK - BIAS)*coefB/Zc, y = 1 + Tc/tau
__device__ __align__(16) float2 g_colstats[BATCH * NPTS];

__device__ __forceinline__ float warpSum(float v) {
#pragma unroll
    for (int o = 16; o > 0; o >>= 1) v += __shfl_xor_sync(0xffffffffu, v, o);
    return v;
}

__device__ __forceinline__ float blockSum(float v, float* sh) {
    __syncthreads();
    v = warpSum(v);
    int w = threadIdx.x >> 5, l = threadIdx.x & 31;
    if (l == 0) sh[w] = v;
    __syncthreads();
    if (threadIdx.x == 0) {
        float x = 0.f;
#pragma unroll
        for (int i = 0; i < THREADS / 32; i++) x += sh[i];
        sh[0] = x;
    }
    __syncthreads();
    return sh[0];
}

__global__ void zero_kernel() {
    if (threadIdx.x < 12) g_acc[threadIdx.x] = 0.f;
}

// ---------------- pointwise losses over B*P points ----------------
__global__ void pointwise_kernel(const float* __restrict__ sp, const float* __restrict__ st,
                                 const float* __restrict__ un, const float* __restrict__ op,
                                 const float* __restrict__ ot, const float* __restrict__ na_,
                                 const float* __restrict__ nb_, int n) {
    float s_l1 = 0.f, s_bce = 0.f, s_unc = 0.f, s_nrm = 0.f;
    for (int i = blockIdx.x * blockDim.x + threadIdx.x; i < n; i += gridDim.x * blockDim.x) {
        s_l1 += fabsf(sp[i] - st[i]);
        float p = op[i], t = ot[i];
        s_bce -= t * __logf(p) + (1.f - t) * __logf(1.f - p);
        float u = un[i];
        s_unc += u * (1.f - u);
        float ax = na_[3 * i], ay = na_[3 * i + 1], az = na_[3 * i + 2];
        float bx = nb_[3 * i], by = nb_[3 * i + 1], bz = nb_[3 * i + 2];
        float nna = sqrtf(fmaf(ax, ax, fmaf(ay, ay, az * az)));
        float nnb = sqrtf(fmaf(bx, bx, fmaf(by, by, bz * bz)));
        float cs = fmaf(ax, bx, fmaf(ay, by, az * bz)) /
                   (fmaxf(nna, 1e-8f) * fmaxf(nnb, 1e-8f));
        s_nrm += 1.f - cs;
    }
    __shared__ float sh[8];
    float v;
    v = blockSum(s_l1, sh);  if (threadIdx.x == 0) atomicAdd(&g_acc[0], v);
    v = blockSum(s_bce, sh); if (threadIdx.x == 0) atomicAdd(&g_acc[1], v);
    v = blockSum(s_unc, sh); if (threadIdx.x == 0) atomicAdd(&g_acc[2], v);
    v = blockSum(s_nrm, sh); if (threadIdx.x == 0) atomicAdd(&g_acc[3], v);
}

// fill (x,y)/z planes from packed xyz global
__device__ __forceinline__ void fill_tile(float2* sxy, float* sz,
                                          const float* __restrict__ base, int t) {
#pragma unroll
    for (int j = 0; j < NPTS / THREADS; j++) {
        int i = t + j * THREADS;
        float x = base[3 * i], y = base[3 * i + 1], z = base[3 * i + 2];
        sxy[i] = make_float2(x, y);
        sz[i] = z;
    }
}

// -------- colstats: QPB target queries per block, online softmax over pred tile --------
__global__ void colstats_kernel(const float* __restrict__ tgt, const float* __restrict__ prd) {
    extern __shared__ float sm[];
    float2* sxy = (float2*)sm;
    float* sz = sm + 2 * NPTS;
    int t = threadIdx.x;
    int b = blockIdx.y;
    int qloc = t / SUBS, sub = t % SUBS;
    int m = blockIdx.x * QPB + qloc;

    fill_tile(sxy, sz, prd + (size_t)b * NPTS * 3, t);
    const float* q = tgt + ((size_t)b * NPTS + m) * 3;
    float px = q[0], py = q[1], pz = q[2];
    __syncthreads();

    float mn = MN_INIT, mnK = MN_INIT * KEXP, Z = 0.f, Su = 0.f;   // mnK finite (7.2e31)
#pragma unroll 4
    for (int j = 0; j < CHUNK; j++) {
        int i = sub + j * SUBS;
        float2 xy = sxy[i];
        float dx = px - xy.x, dy = py - xy.y, dz = pz - sz[i];
        float d2 = fmaxf(fmaf(dx, dx, fmaf(dy, dy, dz * dz)), 1e-12f);
        float r = rsqrtf(d2);
        float d = d2 * r;
        if (d < mn) {
            float f = exp2f(fmaf(d, KEXP, -mnK));
            Z *= f; Su *= f;
            mn = d; mnK = d * KEXP;
        }
        float p = exp2f(fmaf(-d, KEXP, mnK));
        Z += p;
        Su = fmaf(p, d, Su);
    }
    // combine SUBS lanes
    float mnG = mn;
#pragma unroll
    for (int o = 1; o < SUBS; o <<= 1) mnG = fminf(mnG, __shfl_xor_sync(0xffffffffu, mnG, o));
    float f = exp2f(fmaf(mnG, KEXP, -mnK));
    Z *= f; Su *= f;
#pragma unroll
    for (int o = 1; o < SUBS; o <<= 1) {
        Z += __shfl_xor_sync(0xffffffffu, Z, o);
        Su += __shfl_xor_sync(0xffffffffu, Su, o);
    }
    if (sub == 0) {
        float T = Su / Z;
        float qprime = exp2f(fmaf(mnG, KEXP, -BIAS)) * (COEF / Z);
        g_colstats[b * NPTS + m] = make_float2(qprime, fmaf(T, INV_TAU, 1.f));
        atomicAdd(&g_acc[5], mnG);   // chamfer (min over n)
        atomicAdd(&g_acc[7], T);     // EMD column term
    }
}

// -------- rowpass: fused row softmax + full EMD gradient, single sweep --------
__global__ void rowpass_kernel(const float* __restrict__ prd, const float* __restrict__ tgt) {
    extern __shared__ float sm[];
    float2* sxy = (float2*)sm;
    float* sz = sm + 2 * NPTS;
    int t = threadIdx.x;
    int b = blockIdx.y;
    int qloc = t / SUBS, sub = t % SUBS;
    int n = blockIdx.x * QPB + qloc;

    fill_tile(sxy, sz, tgt + (size_t)b * NPTS * 3, t);
    const float* q = prd + ((size_t)b * NPTS + n) * 3;
    float px = q[0], py = q[1], pz = q[2];
    const float2* __restrict__ cst = g_colstats + b * NPTS;
    __syncthreads();

    float mn = MN_INIT, mnK = MN_INIT * KEXP, Z = 0.f, Su = 0.f;   // mnK finite (7.2e31)
    float v1x = 0.f, v1y = 0.f, v1z = 0.f;   // sum p*u        (u = r*dvec)
    float v2x = 0.f, v2y = 0.f, v2z = 0.f;   // sum p*d*u = sum p*dvec  (d*r == 1)
    float gcx = 0.f, gcy = 0.f, gcz = 0.f;   // col-side grad (biased scale)
#pragma unroll 4
    for (int j = 0; j < CHUNK; j++) {
        int i = sub + j * SUBS;
        float2 cs = __ldg(&cst[i]);
        float2 xy = sxy[i];
        float dx = px - xy.x, dy = py - xy.y, dz = pz - sz[i];
        float d2 = fmaxf(fmaf(dx, dx, fmaf(dy, dy, dz * dz)), 1e-12f);
        float r = rsqrtf(d2);
        float d = d2 * r;
        if (d < mn) {
            float f = exp2f(fmaf(d, KEXP, -mnK));
            Z *= f; Su *= f;
            v1x *= f; v1y *= f; v1z *= f;
            v2x *= f; v2y *= f; v2z *= f;
            gcx *= f; gcy *= f; gcz *= f;
            mn = d; mnK = d * KEXP;
        }
        float p = exp2f(fmaf(-d, KEXP, mnK));
        Z += p;
        Su = fmaf(p, d, Su);
        float pr = p * r;
        v1x = fmaf(pr, dx, v1x); v1y = fmaf(pr, dy, v1y); v1z = fmaf(pr, dz, v1z);
        v2x = fmaf(p, dx, v2x);  v2y = fmaf(p, dy, v2y);  v2z = fmaf(p, dz, v2z);
        float t2 = fmaf(cs.y, r, -INV_TAU);    // (cs.y - d/tau)*r, since d*r==1
        float h = (p * cs.x) * t2;
        gcx = fmaf(h, dx, gcx); gcy = fmaf(h, dy, gcy); gcz = fmaf(h, dz, gcz);
    }
    // combine SUBS lanes
    float mnG = mn;
#pragma unroll
    for (int o = 1; o < SUBS; o <<= 1) mnG = fminf(mnG, __shfl_xor_sync(0xffffffffu, mnG, o));
    float f = exp2f(fmaf(mnG, KEXP, -mnK));
    Z *= f; Su *= f;
    v1x *= f; v1y *= f; v1z *= f;
    v2x *= f; v2y *= f; v2z *= f;
    gcx *= f; gcy *= f; gcz *= f;
#pragma unroll
    for (int o = 1; o < SUBS; o <<= 1) {
        Z += __shfl_xor_sync(0xffffffffu, Z, o);
        Su += __shfl_xor_sync(0xffffffffu, Su, o);
        v1x += __shfl_xor_sync(0xffffffffu, v1x, o);
        v1y += __shfl_xor_sync(0xffffffffu, v1y, o);
        v1z += __shfl_xor_sync(0xffffffffu, v1z, o);
        v2x += __shfl_xor_sync(0xffffffffu, v2x, o);
        v2y += __shfl_xor_sync(0xffffffffu, v2y, o);
        v2z += __shfl_xor_sync(0xffffffffu, v2z, o);
        gcx += __shfl_xor_sync(0xffffffffu, gcx, o);
        gcy += __shfl_xor_sync(0xffffffffu, gcy, o);
        gcz += __shfl_xor_sync(0xffffffffu, gcz, o);
    }
    if (sub == 0) {
        float S = Su / Z;
        float c1 = fmaf(S, INV_TAU, 1.f);
        float rs = COEF / Z;
        float colsc = exp2f(fmaf(-mnG, KEXP, BIAS));   // 2^(BIAS - mnG*K)
        float gx = rs * fmaf(c1, v1x, -INV_TAU * v2x) + colsc * gcx;
        float gy = rs * fmaf(c1, v1y, -INV_TAU * v2y) + colsc * gcy;
        float gz = rs * fmaf(c1, v1z, -INV_TAU * v2z) + colsc * gcz;
        float nrm = sqrtf(fmaf(gx, gx, fmaf(gy, gy, gz * gz)));
        atomicAdd(&g_acc[8], fabsf(nrm - 1.f));
        atomicAdd(&g_acc[4], mnG);   // chamfer (min over m)
        atomicAdd(&g_acc[6], S);     // EMD row term
    }
}

// ---------------- finalize ----------------
__global__ void final_kernel(float* __restrict__ out, int bp) {
    float invBP = 1.f / (float)bp;
    float invBN = 1.f / (float)(BATCH * NPTS);
    float l1 = g_acc[0] * invBP;
    float bce = g_acc[1] * invBP;
    float unc = g_acc[2] * invBP;
    float nrm = g_acc[3] * invBP;
    float cham = (g_acc[4] + g_acc[5]) * invBN;
    float emd = (g_acc[6] + g_acc[7]) * invBN;
    float gp = g_acc[8] * invBN;
    float pt = expf(-bce);
    float occ = 0.75f * (1.f - pt) * (1.f - pt) * bce;
    out[0] = l1 + occ + 0.1f * nrm + cham + 0.25f * emd + 0.05f * gp + 0.1f * unc;
}

extern "C" void kernel_launch(void* const* d_in, const int* in_sizes, int n_in,
                              void* d_out, int out_size) {
    const float* sdf_pred   = (const float*)d_in[0];
    const float* sdf_target = (const float*)d_in[1];
    const float* uncertainty = (const float*)d_in[2];
    const float* occ_pred   = (const float*)d_in[3];
    const float* occ_target = (const float*)d_in[4];
    const float* nrm_pred   = (const float*)d_in[5];
    const float* nrm_target = (const float*)d_in[6];
    const float* pc_pred    = (const float*)d_in[7];
    const float* pc_target  = (const float*)d_in[8];
    float* out = (float*)d_out;

    int bp = in_sizes[0];   // B * P = 200000

    cudaFuncSetAttribute(colstats_kernel, cudaFuncAttributeMaxDynamicSharedMemorySize,
                         (int)TILE_BYTES);
    cudaFuncSetAttribute(rowpass_kernel, cudaFuncAttributeMaxDynamicSharedMemorySize,
                         (int)TILE_BYTES);

    zero_kernel<<<1, 32>>>();
    pointwise_kernel<<<448, THREADS>>>(sdf_pred, sdf_target, uncertainty,
                                       occ_pred, occ_target, nrm_pred, nrm_target, bp);
    dim3 grid(NPTS / QPB, BATCH);   // 256 x 2 = 512 blocks
    colstats_kernel<<<grid, THREADS, TILE_BYTES>>>(pc_target, pc_pred);
    rowpass_kernel<<<grid, THREADS, TILE_BYTES>>>(pc_pred, pc_target);
    final_kernel<<<1, 1>>>(out, bp);
}

// round 10
// speedup vs baseline: 1.6976x; 1.0941x over previous
#include <cuda_runtime.h>
#include <math.h>

#define THREADS 256
#define NPTS 4096
#define BATCH 2
#define QPB 16                 // queries per block
#define SUBS 16                // threads per query
#define CHUNK (NPTS / SUBS)    // 256 opponents per thread
#define INV_TAU 50.0f
#define KEXP 72.13475204444817f   // 1/(TAU*ln2): exp(x/TAU) = exp2(x*KEXP)
#define BIAS 32.0f
#define COEF (1.0f / (float)(BATCH * NPTS))
#define MN_INIT 1e30f

// tile: float2 (x,y) plane [NPTS] + float z plane [NPTS] = 48KB
#define TILE_BYTES (NPTS * sizeof(float2) + NPTS * sizeof(float))

// raw HW approximations (single MUFU op each)
__device__ __forceinline__ float ex2(float x) {
    float y;
    asm("ex2.approx.ftz.f32 %0, %1;" : "=f"(y) : "f"(x));
    return y;
}
__device__ __forceinline__ float rsq(float x) {
    float y;
    asm("rsqrt.approx.f32 %0, %1;" : "=f"(y) : "f"(x));
    return y;
}

// accumulators: 0 l1, 1 bce, 2 unc, 3 normal, 4 chamfer_row, 5 chamfer_col,
//               6 S-sum (EMD row), 7 T-sum (EMD col), 8 gp
__device__ float g_acc[12];
// per (batch, target m): x = 2^(colminK - BIAS)*coefB/Zc, y = 1 + Tc/tau
__device__ __align__(16) float2 g_colstats[BATCH * NPTS];

__device__ __forceinline__ float warpSum(float v) {
#pragma unroll
    for (int o = 16; o > 0; o >>= 1) v += __shfl_xor_sync(0xffffffffu, v, o);
    return v;
}

__device__ __forceinline__ float blockSum(float v, float* sh) {
    __syncthreads();
    v = warpSum(v);
    int w = threadIdx.x >> 5, l = threadIdx.x & 31;
    if (l == 0) sh[w] = v;
    __syncthreads();
    if (threadIdx.x == 0) {
        float x = 0.f;
#pragma unroll
        for (int i = 0; i < THREADS / 32; i++) x += sh[i];
        sh[0] = x;
    }
    __syncthreads();
    return sh[0];
}

__global__ void zero_kernel() {
    if (threadIdx.x < 12) g_acc[threadIdx.x] = 0.f;
}

// ---------------- pointwise losses over B*P points ----------------
__global__ void pointwise_kernel(const float* __restrict__ sp, const float* __restrict__ st,
                                 const float* __restrict__ un, const float* __restrict__ op,
                                 const float* __restrict__ ot, const float* __restrict__ na_,
                                 const float* __restrict__ nb_, int n) {
    float s_l1 = 0.f, s_bce = 0.f, s_unc = 0.f, s_nrm = 0.f;
    for (int i = blockIdx.x * blockDim.x + threadIdx.x; i < n; i += gridDim.x * blockDim.x) {
        s_l1 += fabsf(sp[i] - st[i]);
        float p = op[i], t = ot[i];
        s_bce -= t * __logf(p) + (1.f - t) * __logf(1.f - p);
        float u = un[i];
        s_unc += u * (1.f - u);
        float ax = na_[3 * i], ay = na_[3 * i + 1], az = na_[3 * i + 2];
        float bx = nb_[3 * i], by = nb_[3 * i + 1], bz = nb_[3 * i + 2];
        float nna2 = fmaf(ax, ax, fmaf(ay, ay, az * az));
        float nnb2 = fmaf(bx, bx, fmaf(by, by, bz * bz));
        float inv = rsq(fmaxf(nna2, 1e-16f)) * rsq(fmaxf(nnb2, 1e-16f));
        float cs = fmaf(ax, bx, fmaf(ay, by, az * bz)) * inv;
        s_nrm += 1.f - cs;
    }
    __shared__ float sh[8];
    float v;
    v = blockSum(s_l1, sh);  if (threadIdx.x == 0) atomicAdd(&g_acc[0], v);
    v = blockSum(s_bce, sh); if (threadIdx.x == 0) atomicAdd(&g_acc[1], v);
    v = blockSum(s_unc, sh); if (threadIdx.x == 0) atomicAdd(&g_acc[2], v);
    v = blockSum(s_nrm, sh); if (threadIdx.x == 0) atomicAdd(&g_acc[3], v);
}

// fill (x,y)/z planes from packed xyz global
__device__ __forceinline__ void fill_tile(float2* sxy, float* sz,
                                          const float* __restrict__ base, int t) {
#pragma unroll
    for (int j = 0; j < NPTS / THREADS; j++) {
        int i = t + j * THREADS;
        float x = base[3 * i], y = base[3 * i + 1], z = base[3 * i + 2];
        sxy[i] = make_float2(x, y);
        sz[i] = z;
    }
}

// -------- colstats: QPB target queries per block, online softmax over pred tile --------
__global__ void colstats_kernel(const float* __restrict__ tgt, const float* __restrict__ prd) {
    extern __shared__ float sm[];
    float2* sxy = (float2*)sm;
    float* sz = sm + 2 * NPTS;
    int t = threadIdx.x;
    int b = blockIdx.y;
    int qloc = t / SUBS, sub = t % SUBS;
    int m = blockIdx.x * QPB + qloc;

    fill_tile(sxy, sz, prd + (size_t)b * NPTS * 3, t);
    const float* q = tgt + ((size_t)b * NPTS + m) * 3;
    float px = q[0], py = q[1], pz = q[2];
    __syncthreads();

    float mn = MN_INIT, mnK = MN_INIT * KEXP, Z = 0.f, Su = 0.f;   // mnK finite (7.2e31)
#pragma unroll 4
    for (int j = 0; j < CHUNK; j++) {
        int i = sub + j * SUBS;
        float2 xy = sxy[i];
        float dx = px - xy.x, dy = py - xy.y, dz = pz - sz[i];
        float d2 = fmaxf(fmaf(dx, dx, fmaf(dy, dy, dz * dz)), 1e-12f);
        float r = rsq(d2);
        float d = d2 * r;
        if (d < mn) {
            float f = ex2(fmaf(d, KEXP, -mnK));
            Z *= f; Su *= f;
            mn = d; mnK = d * KEXP;
        }
        float p = ex2(fmaf(-d, KEXP, mnK));
        Z += p;
        Su = fmaf(p, d, Su);
    }
    // combine SUBS lanes
    float mnG = mn;
#pragma unroll
    for (int o = 1; o < SUBS; o <<= 1) mnG = fminf(mnG, __shfl_xor_sync(0xffffffffu, mnG, o));
    float f = ex2(fmaf(mnG, KEXP, -mnK));
    Z *= f; Su *= f;
#pragma unroll
    for (int o = 1; o < SUBS; o <<= 1) {
        Z += __shfl_xor_sync(0xffffffffu, Z, o);
        Su += __shfl_xor_sync(0xffffffffu, Su, o);
    }
    if (sub == 0) {
        float T = Su / Z;
        float qprime = ex2(fmaf(mnG, KEXP, -BIAS)) * (COEF / Z);
        g_colstats[b * NPTS + m] = make_float2(qprime, fmaf(T, INV_TAU, 1.f));
        atomicAdd(&g_acc[5], mnG);   // chamfer (min over n)
        atomicAdd(&g_acc[7], T);     // EMD column term
    }
}

// -------- rowpass: fused row softmax + full EMD gradient, single sweep --------
__global__ void rowpass_kernel(const float* __restrict__ prd, const float* __restrict__ tgt) {
    extern __shared__ float sm[];
    float2* sxy = (float2*)sm;
    float* sz = sm + 2 * NPTS;
    int t = threadIdx.x;
    int b = blockIdx.y;
    int qloc = t / SUBS, sub = t % SUBS;
    int n = blockIdx.x * QPB + qloc;

    fill_tile(sxy, sz, tgt + (size_t)b * NPTS * 3, t);
    const float* q = prd + ((size_t)b * NPTS + n) * 3;
    float px = q[0], py = q[1], pz = q[2];
    const float2* __restrict__ cst = g_colstats + b * NPTS;
    __syncthreads();

    float mn = MN_INIT, mnK = MN_INIT * KEXP, Z = 0.f, Su = 0.f;   // mnK finite (7.2e31)
    float v1x = 0.f, v1y = 0.f, v1z = 0.f;   // sum p*u        (u = r*dvec)
    float v2x = 0.f, v2y = 0.f, v2z = 0.f;   // sum p*d*u = sum p*dvec  (d*r == 1)
    float gcx = 0.f, gcy = 0.f, gcz = 0.f;   // col-side grad (biased scale)
#pragma unroll 4
    for (int j = 0; j < CHUNK; j++) {
        int i = sub + j * SUBS;
        float2 cs = __ldg(&cst[i]);
        float2 xy = sxy[i];
        float dx = px - xy.x, dy = py - xy.y, dz = pz - sz[i];
        float d2 = fmaxf(fmaf(dx, dx, fmaf(dy, dy, dz * dz)), 1e-12f);
        float r = rsq(d2);
        float d = d2 * r;
        if (d < mn) {
            float f = ex2(fmaf(d, KEXP, -mnK));
            Z *= f; Su *= f;
            v1x *= f; v1y *= f; v1z *= f;
            v2x *= f; v2y *= f; v2z *= f;
            gcx *= f; gcy *= f; gcz *= f;
            mn = d; mnK = d * KEXP;
        }
        float p = ex2(fmaf(-d, KEXP, mnK));
        Z += p;
        Su = fmaf(p, d, Su);
        float pr = p * r;
        v1x = fmaf(pr, dx, v1x); v1y = fmaf(pr, dy, v1y); v1z = fmaf(pr, dz, v1z);
        v2x = fmaf(p, dx, v2x);  v2y = fmaf(p, dy, v2y);  v2z = fmaf(p, dz, v2z);
        float t2 = fmaf(cs.y, r, -INV_TAU);    // (cs.y - d/tau)*r, since d*r==1
        float h = (p * cs.x) * t2;
        gcx = fmaf(h, dx, gcx); gcy = fmaf(h, dy, gcy); gcz = fmaf(h, dz, gcz);
    }
    // combine SUBS lanes
    float mnG = mn;
#pragma unroll
    for (int o = 1; o < SUBS; o <<= 1) mnG = fminf(mnG, __shfl_xor_sync(0xffffffffu, mnG, o));
    float f = ex2(fmaf(mnG, KEXP, -mnK));
    Z *= f; Su *= f;
    v1x *= f; v1y *= f; v1z *= f;
    v2x *= f; v2y *= f; v2z *= f;
    gcx *= f; gcy *= f; gcz *= f;
#pragma unroll
    for (int o = 1; o < SUBS; o <<= 1) {
        Z += __shfl_xor_sync(0xffffffffu, Z, o);
        Su += __shfl_xor_sync(0xffffffffu, Su, o);
        v1x += __shfl_xor_sync(0xffffffffu, v1x, o);
        v1y += __shfl_xor_sync(0xffffffffu, v1y, o);
        v1z += __shfl_xor_sync(0xffffffffu, v1z, o);
        v2x += __shfl_xor_sync(0xffffffffu, v2x, o);
        v2y += __shfl_xor_sync(0xffffffffu, v2y, o);
        v2z += __shfl_xor_sync(0xffffffffu, v2z, o);
        gcx += __shfl_xor_sync(0xffffffffu, gcx, o);
        gcy += __shfl_xor_sync(0xffffffffu, gcy, o);
        gcz += __shfl_xor_sync(0xffffffffu, gcz, o);
    }
    if (sub == 0) {
        float S = Su / Z;
        float c1 = fmaf(S, INV_TAU, 1.f);
        float rs = COEF / Z;
        float colsc = ex2(fmaf(-mnG, KEXP, BIAS));   // 2^(BIAS - mnG*K)
        float gx = rs * fmaf(c1, v1x, -INV_TAU * v2x) + colsc * gcx;
        float gy = rs * fmaf(c1, v1y, -INV_TAU * v2y) + colsc * gcy;
        float gz = rs * fmaf(c1, v1z, -INV_TAU * v2z) + colsc * gcz;
        float nrm = sqrtf(fmaf(gx, gx, fmaf(gy, gy, gz * gz)));
        atomicAdd(&g_acc[8], fabsf(nrm - 1.f));
        atomicAdd(&g_acc[4], mnG);   // chamfer (min over m)
        atomicAdd(&g_acc[6], S);     // EMD row term
    }
}

// ---------------- finalize ----------------
__global__ void final_kernel(float* __restrict__ out, int bp) {
    float invBP = 1.f / (float)bp;
    float invBN = 1.f / (float)(BATCH * NPTS);
    float l1 = g_acc[0] * invBP;
    float bce = g_acc[1] * invBP;
    float unc = g_acc[2] * invBP;
    float nrm = g_acc[3] * invBP;
    float cham = (g_acc[4] + g_acc[5]) * invBN;
    float emd = (g_acc[6] + g_acc[7]) * invBN;
    float gp = g_acc[8] * invBN;
    float pt = expf(-bce);
    float occ = 0.75f * (1.f - pt) * (1.f - pt) * bce;
    out[0] = l1 + occ + 0.1f * nrm + cham + 0.25f * emd + 0.05f * gp + 0.1f * unc;
}

extern "C" void kernel_launch(void* const* d_in, const int* in_sizes, int n_in,
                              void* d_out, int out_size) {
    const float* sdf_pred   = (const float*)d_in[0];
    const float* sdf_target = (const float*)d_in[1];
    const float* uncertainty = (const float*)d_in[2];
    const float* occ_pred   = (const float*)d_in[3];
    const float* occ_target = (const float*)d_in[4];
    const float* nrm_pred   = (const float*)d_in[5];
    const float* nrm_target = (const float*)d_in[6];
    const float* pc_pred    = (const float*)d_in[7];
    const float* pc_target  = (const float*)d_in[8];
    float* out = (float*)d_out;

    int bp = in_sizes[0];   // B * P = 200000

    cudaFuncSetAttribute(colstats_kernel, cudaFuncAttributeMaxDynamicSharedMemorySize,
                         (int)TILE_BYTES);
    cudaFuncSetAttribute(rowpass_kernel, cudaFuncAttributeMaxDynamicSharedMemorySize,
                         (int)TILE_BYTES);

    zero_kernel<<<1, 32>>>();
    pointwise_kernel<<<448, THREADS>>>(sdf_pred, sdf_target, uncertainty,
                                       occ_pred, occ_target, nrm_pred, nrm_target, bp);
    dim3 grid(NPTS / QPB, BATCH);   // 256 x 2 = 512 blocks
    colstats_kernel<<<grid, THREADS, TILE_BYTES>>>(pc_target, pc_pred);
    rowpass_kernel<<<grid, THREADS, TILE_BYTES>>>(pc_pred, pc_target);
    final_kernel<<<1, 1>>>(out, bp);
}

// round 11
// speedup vs baseline: 1.7928x; 1.0561x over previous
#include <cuda_runtime.h>
#include <math.h>

#define THREADS 256
#define NPTS 4096
#define BATCH 2
#define QPB 16                 // queries per block
#define SUBS 16                // threads per query
#define CHUNK (NPTS / SUBS)    // 256 opponents per thread
#define INV_TAU 50.0f
#define KEXP 72.13475204444817f   // 1/(TAU*ln2): exp(x/TAU) = exp2(x*KEXP)
#define NKEXP (-72.13475204444817f)
#define COEF (1.0f / (float)(BATCH * NPTS))

// tile: float2 (x,y) plane [NPTS] + float z plane [NPTS] = 48KB
#define TILE_BYTES (NPTS * sizeof(float2) + NPTS * sizeof(float))

// raw HW approximations (single MUFU op each)
__device__ __forceinline__ float ex2(float x) {
    float y;
    asm("ex2.approx.ftz.f32 %0, %1;" : "=f"(y) : "f"(x));
    return y;
}
__device__ __forceinline__ float rsq(float x) {
    float y;
    asm("rsqrt.approx.f32 %0, %1;" : "=f"(y) : "f"(x));
    return y;
}

// accumulators: 0 l1, 1 bce, 2 unc, 3 normal, 4 chamfer_row, 5 chamfer_col,
//               6 S-sum (EMD row), 7 T-sum (EMD col), 8 gp
__device__ float g_acc[12];
// per (batch, target m): x = COEF/Zc_raw, y = 1 + Tc/tau
__device__ __align__(16) float2 g_colstats[BATCH * NPTS];

__device__ __forceinline__ float warpSum(float v) {
#pragma unroll
    for (int o = 16; o > 0; o >>= 1) v += __shfl_xor_sync(0xffffffffu, v, o);
    return v;
}

__device__ __forceinline__ float blockSum(float v, float* sh) {
    __syncthreads();
    v = warpSum(v);
    int w = threadIdx.x >> 5, l = threadIdx.x & 31;
    if (l == 0) sh[w] = v;
    __syncthreads();
    if (threadIdx.x == 0) {
        float x = 0.f;
#pragma unroll
        for (int i = 0; i < THREADS / 32; i++) x += sh[i];
        sh[0] = x;
    }
    __syncthreads();
    return sh[0];
}

__global__ void zero_kernel() {
    if (threadIdx.x < 12) g_acc[threadIdx.x] = 0.f;
}

// ---------------- pointwise losses over B*P points ----------------
__global__ void pointwise_kernel(const float* __restrict__ sp, const float* __restrict__ st,
                                 const float* __restrict__ un, const float* __restrict__ op,
                                 const float* __restrict__ ot, const float* __restrict__ na_,
                                 const float* __restrict__ nb_, int n) {
    float s_l1 = 0.f, s_bce = 0.f, s_unc = 0.f, s_nrm = 0.f;
    for (int i = blockIdx.x * blockDim.x + threadIdx.x; i < n; i += gridDim.x * blockDim.x) {
        s_l1 += fabsf(sp[i] - st[i]);
        float p = op[i], t = ot[i];
        s_bce -= t * __logf(p) + (1.f - t) * __logf(1.f - p);
        float u = un[i];
        s_unc += u * (1.f - u);
        float ax = na_[3 * i], ay = na_[3 * i + 1], az = na_[3 * i + 2];
        float bx = nb_[3 * i], by = nb_[3 * i + 1], bz = nb_[3 * i + 2];
        float nna2 = fmaf(ax, ax, fmaf(ay, ay, az * az));
        float nnb2 = fmaf(bx, bx, fmaf(by, by, bz * bz));
        float inv = rsq(fmaxf(nna2, 1e-16f)) * rsq(fmaxf(nnb2, 1e-16f));
        float cs = fmaf(ax, bx, fmaf(ay, by, az * bz)) * inv;
        s_nrm += 1.f - cs;
    }
    __shared__ float sh[8];
    float v;
    v = blockSum(s_l1, sh);  if (threadIdx.x == 0) atomicAdd(&g_acc[0], v);
    v = blockSum(s_bce, sh); if (threadIdx.x == 0) atomicAdd(&g_acc[1], v);
    v = blockSum(s_unc, sh); if (threadIdx.x == 0) atomicAdd(&g_acc[2], v);
    v = blockSum(s_nrm, sh); if (threadIdx.x == 0) atomicAdd(&g_acc[3], v);
}

// fill (x,y)/z planes from packed xyz global
__device__ __forceinline__ void fill_tile(float2* sxy, float* sz,
                                          const float* __restrict__ base, int t) {
#pragma unroll
    for (int j = 0; j < NPTS / THREADS; j++) {
        int i = t + j * THREADS;
        float x = base[3 * i], y = base[3 * i + 1], z = base[3 * i + 2];
        sxy[i] = make_float2(x, y);
        sz[i] = z;
    }
}

// -------- colstats: QPB target queries per block, raw (unshifted) softmax --------
__global__ void colstats_kernel(const float* __restrict__ tgt, const float* __restrict__ prd) {
    extern __shared__ float sm[];
    float2* sxy = (float2*)sm;
    float* sz = sm + 2 * NPTS;
    int t = threadIdx.x;
    int b = blockIdx.y;
    int qloc = t / SUBS, sub = t % SUBS;
    int m = blockIdx.x * QPB + qloc;

    fill_tile(sxy, sz, prd + (size_t)b * NPTS * 3, t);
    const float* q = tgt + ((size_t)b * NPTS + m) * 3;
    float px = q[0], py = q[1], pz = q[2];
    __syncthreads();

    float mn2 = 1e30f, Z = 0.f, Su = 0.f;
#pragma unroll 4
    for (int j = 0; j < CHUNK; j++) {
        int i = sub + j * SUBS;
        float2 xy = sxy[i];
        float dx = px - xy.x, dy = py - xy.y, dz = pz - sz[i];
        float d2 = fmaxf(fmaf(dx, dx, fmaf(dy, dy, dz * dz)), 1e-12f);
        mn2 = fminf(mn2, d2);
        float r = rsq(d2);
        float d = d2 * r;
        float p = ex2(d * NKEXP);   // raw scale; tau=0.02 decay makes shift unnecessary
        Z += p;
        Su = fmaf(p, d, Su);
    }
    // combine SUBS lanes
#pragma unroll
    for (int o = 1; o < SUBS; o <<= 1) {
        mn2 = fminf(mn2, __shfl_xor_sync(0xffffffffu, mn2, o));
        Z += __shfl_xor_sync(0xffffffffu, Z, o);
        Su += __shfl_xor_sync(0xffffffffu, Su, o);
    }
    if (sub == 0) {
        float T = Su / Z;
        g_colstats[b * NPTS + m] = make_float2(COEF / Z, fmaf(T, INV_TAU, 1.f));
        atomicAdd(&g_acc[5], sqrtf(mn2));   // chamfer (min over n)
        atomicAdd(&g_acc[7], T);            // EMD column term
    }
}

// -------- rowpass: fused row softmax + full EMD gradient, branch-free sweep --------
__global__ void rowpass_kernel(const float* __restrict__ prd, const float* __restrict__ tgt) {
    extern __shared__ float sm[];
    float2* sxy = (float2*)sm;
    float* sz = sm + 2 * NPTS;
    int t = threadIdx.x;
    int b = blockIdx.y;
    int qloc = t / SUBS, sub = t % SUBS;
    int n = blockIdx.x * QPB + qloc;

    fill_tile(sxy, sz, tgt + (size_t)b * NPTS * 3, t);
    const float* q = prd + ((size_t)b * NPTS + n) * 3;
    float px = q[0], py = q[1], pz = q[2];
    const float2* __restrict__ cst = g_colstats + b * NPTS;
    __syncthreads();

    float mn2 = 1e30f, Z = 0.f, Su = 0.f;
    float v1x = 0.f, v1y = 0.f, v1z = 0.f;   // sum p*u        (u = r*dvec)
    float v2x = 0.f, v2y = 0.f, v2z = 0.f;   // sum p*dvec     (= p*d*u since d*r==1)
    float gcx = 0.f, gcy = 0.f, gcz = 0.f;   // col-side grad (already COEF/Zc scaled)
#pragma unroll 4
    for (int j = 0; j < CHUNK; j++) {
        int i = sub + j * SUBS;
        float2 cs = __ldg(&cst[i]);
        float2 xy = sxy[i];
        float dx = px - xy.x, dy = py - xy.y, dz = pz - sz[i];
        float d2 = fmaxf(fmaf(dx, dx, fmaf(dy, dy, dz * dz)), 1e-12f);
        mn2 = fminf(mn2, d2);
        float r = rsq(d2);
        float d = d2 * r;
        float p = ex2(d * NKEXP);   // raw scale
        Z += p;
        Su = fmaf(p, d, Su);
        float pr = p * r;
        v1x = fmaf(pr, dx, v1x); v1y = fmaf(pr, dy, v1y); v1z = fmaf(pr, dz, v1z);
        v2x = fmaf(p, dx, v2x);  v2y = fmaf(p, dy, v2y);  v2z = fmaf(p, dz, v2z);
        float t2 = fmaf(cs.y, r, -INV_TAU);    // (cs.y - d/tau)*r, since d*r==1
        float h = (p * cs.x) * t2;
        gcx = fmaf(h, dx, gcx); gcy = fmaf(h, dy, gcy); gcz = fmaf(h, dz, gcz);
    }
    // combine SUBS lanes
#pragma unroll
    for (int o = 1; o < SUBS; o <<= 1) {
        mn2 = fminf(mn2, __shfl_xor_sync(0xffffffffu, mn2, o));
        Z += __shfl_xor_sync(0xffffffffu, Z, o);
        Su += __shfl_xor_sync(0xffffffffu, Su, o);
        v1x += __shfl_xor_sync(0xffffffffu, v1x, o);
        v1y += __shfl_xor_sync(0xffffffffu, v1y, o);
        v1z += __shfl_xor_sync(0xffffffffu, v1z, o);
        v2x += __shfl_xor_sync(0xffffffffu, v2x, o);
        v2y += __shfl_xor_sync(0xffffffffu, v2y, o);
        v2z += __shfl_xor_sync(0xffffffffu, v2z, o);
        gcx += __shfl_xor_sync(0xffffffffu, gcx, o);
        gcy += __shfl_xor_sync(0xffffffffu, gcy, o);
        gcz += __shfl_xor_sync(0xffffffffu, gcz, o);
    }
    if (sub == 0) {
        float S = Su / Z;
        float c1 = fmaf(S, INV_TAU, 1.f);
        float rs = COEF / Z;
        float gx = rs * fmaf(c1, v1x, -INV_TAU * v2x) + gcx;
        float gy = rs * fmaf(c1, v1y, -INV_TAU * v2y) + gcy;
        float gz = rs * fmaf(c1, v1z, -INV_TAU * v2z) + gcz;
        float nrm = sqrtf(fmaf(gx, gx, fmaf(gy, gy, gz * gz)));
        atomicAdd(&g_acc[8], fabsf(nrm - 1.f));
        atomicAdd(&g_acc[4], sqrtf(mn2));   // chamfer (min over m)
        atomicAdd(&g_acc[6], S);            // EMD row term
    }
}

// ---------------- finalize ----------------
__global__ void final_kernel(float* __restrict__ out, int bp) {
    float invBP = 1.f / (float)bp;
    float invBN = 1.f / (float)(BATCH * NPTS);
    float l1 = g_acc[0] * invBP;
    float bce = g_acc[1] * invBP;
    float unc = g_acc[2] * invBP;
    float nrm = g_acc[3] * invBP;
    float cham = (g_acc[4] + g_acc[5]) * invBN;
    float emd = (g_acc[6] + g_acc[7]) * invBN;
    float gp = g_acc[8] * invBN;
    float pt = expf(-bce);
    float occ = 0.75f * (1.f - pt) * (1.f - pt) * bce;
    out[0] = l1 + occ + 0.1f * nrm + cham + 0.25f * emd + 0.05f * gp + 0.1f * unc;
}

extern "C" void kernel_launch(void* const* d_in, const int* in_sizes, int n_in,
                              void* d_out, int out_size) {
    const float* sdf_pred   = (const float*)d_in[0];
    const float* sdf_target = (const float*)d_in[1];
    const float* uncertainty = (const float*)d_in[2];
    const float* occ_pred   = (const float*)d_in[3];
    const float* occ_target = (const float*)d_in[4];
    const float* nrm_pred   = (const float*)d_in[5];
    const float* nrm_target = (const float*)d_in[6];
    const float* pc_pred    = (const float*)d_in[7];
    const float* pc_target  = (const float*)d_in[8];
    float* out = (float*)d_out;

    int bp = in_sizes[0];   // B * P = 200000

    cudaFuncSetAttribute(colstats_kernel, cudaFuncAttributeMaxDynamicSharedMemorySize,
                         (int)TILE_BYTES);
    cudaFuncSetAttribute(rowpass_kernel, cudaFuncAttributeMaxDynamicSharedMemorySize,
                         (int)TILE_BYTES);

    zero_kernel<<<1, 32>>>();
    pointwise_kernel<<<448, THREADS>>>(sdf_pred, sdf_target, uncertainty,
                                       occ_pred, occ_target, nrm_pred, nrm_target, bp);
    dim3 grid(NPTS / QPB, BATCH);   // 256 x 2 = 512 blocks
    colstats_kernel<<<grid, THREADS, TILE_BYTES>>>(pc_target, pc_pred);
    rowpass_kernel<<<grid, THREADS, TILE_BYTES>>>(pc_pred, pc_target);
    final_kernel<<<1, 1>>>(out, bp);
}

// round 12
// speedup vs baseline: 1.8850x; 1.0514x over previous
#include <cuda_runtime.h>
#include <math.h>

#define THREADS 256
#define NPTS 4096
#define NPAIRS (NPTS / 2)        // 2048
#define BATCH 2
#define QPB 16                   // queries per block
#define SUBS 16                  // threads per query
#define PCHUNK (NPAIRS / SUBS)   // 128 pairs per thread
#define INV_TAU 50.0f
#define NKEXP (-72.13475204444817f)   // -1/(TAU*ln2)
#define COEF (1.0f / (float)(BATCH * NPTS))

// tile: float4 xy-pairs [NPAIRS] + float2 z-pairs [NPAIRS] = 48KB
#define TILE_BYTES (NPAIRS * sizeof(float4) + NPAIRS * sizeof(float2))

// raw HW approximations (single MUFU op each)
__device__ __forceinline__ float ex2(float x) {
    float y;
    asm("ex2.approx.ftz.f32 %0, %1;" : "=f"(y) : "f"(x));
    return y;
}
__device__ __forceinline__ float rsq(float x) {
    float y;
    asm("rsqrt.approx.f32 %0, %1;" : "=f"(y) : "f"(x));
    return y;
}

// accumulators: 0 l1, 1 bce, 2 unc, 3 normal, 4 chamfer_row, 5 chamfer_col,
//               6 S-sum (EMD row), 7 T-sum (EMD col), 8 gp
__device__ float g_acc[12];
// [0] = colstats (per target m), [1] = rowstats (per pred n)
// each entry: x = COEF/Z_raw, y = 1 + (Su/Z)*INV_TAU
__device__ __align__(16) float2 g_stats[2][BATCH * NPTS];

__device__ __forceinline__ float warpSum(float v) {
#pragma unroll
    for (int o = 16; o > 0; o >>= 1) v += __shfl_xor_sync(0xffffffffu, v, o);
    return v;
}

__device__ __forceinline__ float blockSum(float v, float* sh) {
    __syncthreads();
    v = warpSum(v);
    int w = threadIdx.x >> 5, l = threadIdx.x & 31;
    if (l == 0) sh[w] = v;
    __syncthreads();
    if (threadIdx.x == 0) {
        float x = 0.f;
#pragma unroll
        for (int i = 0; i < THREADS / 32; i++) x += sh[i];
        sh[0] = x;
    }
    __syncthreads();
    return sh[0];
}

__global__ void zero_kernel() {
    if (threadIdx.x < 12) g_acc[threadIdx.x] = 0.f;
}

// ---------------- pointwise losses over B*P points ----------------
__global__ void pointwise_kernel(const float* __restrict__ sp, const float* __restrict__ st,
                                 const float* __restrict__ un, const float* __restrict__ op,
                                 const float* __restrict__ ot, const float* __restrict__ na_,
                                 const float* __restrict__ nb_, int n) {
    float s_l1 = 0.f, s_bce = 0.f, s_unc = 0.f, s_nrm = 0.f;
    for (int i = blockIdx.x * blockDim.x + threadIdx.x; i < n; i += gridDim.x * blockDim.x) {
        s_l1 += fabsf(sp[i] - st[i]);
        float p = op[i], t = ot[i];
        s_bce -= t * __logf(p) + (1.f - t) * __logf(1.f - p);
        float u = un[i];
        s_unc += u * (1.f - u);
        float ax = na_[3 * i], ay = na_[3 * i + 1], az = na_[3 * i + 2];
        float bx = nb_[3 * i], by = nb_[3 * i + 1], bz = nb_[3 * i + 2];
        float nna2 = fmaf(ax, ax, fmaf(ay, ay, az * az));
        float nnb2 = fmaf(bx, bx, fmaf(by, by, bz * bz));
        float inv = rsq(fmaxf(nna2, 1e-16f)) * rsq(fmaxf(nnb2, 1e-16f));
        float cs = fmaf(ax, bx, fmaf(ay, by, az * bz)) * inv;
        s_nrm += 1.f - cs;
    }
    __shared__ float sh[8];
    float v;
    v = blockSum(s_l1, sh);  if (threadIdx.x == 0) atomicAdd(&g_acc[0], v);
    v = blockSum(s_bce, sh); if (threadIdx.x == 0) atomicAdd(&g_acc[1], v);
    v = blockSum(s_unc, sh); if (threadIdx.x == 0) atomicAdd(&g_acc[2], v);
    v = blockSum(s_nrm, sh); if (threadIdx.x == 0) atomicAdd(&g_acc[3], v);
}

// pack opponent cloud into pair planes: float4(x0,y0,x1,y1), float2(z0,z1)
__device__ __forceinline__ void fill_pairs(float4* sxy4, float2* sz2,
                                           const float* __restrict__ base, int t) {
#pragma unroll
    for (int j = 0; j < NPAIRS / THREADS; j++) {   // 8
        int p = t + j * THREADS;
        const float* s = base + 6 * p;
        sxy4[p] = make_float4(s[0], s[1], s[3], s[4]);
        sz2[p] = make_float2(s[2], s[5]);
    }
}

// -------- stats: softmax stats per query point over opponent tile --------
// side 0: queries = targets, opponents = preds (col stats)
// side 1: queries = preds, opponents = targets (row stats)
__global__ void stats_kernel(const float* __restrict__ prd, const float* __restrict__ tgt) {
    extern __shared__ float sm[];
    float4* sxy4 = (float4*)sm;
    float2* sz2 = (float2*)(sm + 4 * NPAIRS);
    int t = threadIdx.x;
    int b = blockIdx.y;
    int side = blockIdx.z;
    const float* qbase = side == 0 ? tgt : prd;
    const float* obase = side == 0 ? prd : tgt;
    int qloc = t / SUBS, sub = t % SUBS;
    int m = blockIdx.x * QPB + qloc;

    fill_pairs(sxy4, sz2, obase + (size_t)b * NPTS * 3, t);
    const float* q = qbase + ((size_t)b * NPTS + m) * 3;
    float px = q[0], py = q[1], pz = q[2];
    __syncthreads();

    float mn2 = 1e30f, Z = 0.f, Su = 0.f;
#pragma unroll 2
    for (int j = 0; j < PCHUNK; j++) {
        int pi = sub + j * SUBS;
        float4 xy = sxy4[pi];
        float2 zz = sz2[pi];
        // element A
        float dx = px - xy.x, dy = py - xy.y, dz = pz - zz.x;
        float d2 = fmaxf(fmaf(dx, dx, fmaf(dy, dy, dz * dz)), 1e-12f);
        mn2 = fminf(mn2, d2);
        float r = rsq(d2);
        float d = d2 * r;
        float p = ex2(d * NKEXP);
        Z += p;
        Su = fmaf(p, d, Su);
        // element B
        float ex = px - xy.z, ey = py - xy.w, ez = pz - zz.y;
        float e2 = fmaxf(fmaf(ex, ex, fmaf(ey, ey, ez * ez)), 1e-12f);
        mn2 = fminf(mn2, e2);
        float r2 = rsq(e2);
        float e = e2 * r2;
        float pe = ex2(e * NKEXP);
        Z += pe;
        Su = fmaf(pe, e, Su);
    }
    // combine SUBS lanes
#pragma unroll
    for (int o = 1; o < SUBS; o <<= 1) {
        mn2 = fminf(mn2, __shfl_xor_sync(0xffffffffu, mn2, o));
        Z += __shfl_xor_sync(0xffffffffu, Z, o);
        Su += __shfl_xor_sync(0xffffffffu, Su, o);
    }
    if (sub == 0) {
        float T = Su / Z;
        g_stats[side][b * NPTS + m] = make_float2(COEF / Z, fmaf(T, INV_TAU, 1.f));
        atomicAdd(&g_acc[5 - side], sqrtf(mn2));   // chamfer
        atomicAdd(&g_acc[7 - side], T);            // EMD term
    }
}

// -------- grad: EMD gradient penalty with precomputed row & col stats --------
__global__ void grad_kernel(const float* __restrict__ prd, const float* __restrict__ tgt) {
    extern __shared__ float sm[];
    float4* sxy4 = (float4*)sm;
    float2* sz2 = (float2*)(sm + 4 * NPAIRS);
    int t = threadIdx.x;
    int b = blockIdx.y;
    int qloc = t / SUBS, sub = t % SUBS;
    int n = blockIdx.x * QPB + qloc;

    fill_pairs(sxy4, sz2, tgt + (size_t)b * NPTS * 3, t);
    const float* q = prd + ((size_t)b * NPTS + n) * 3;
    float px = q[0], py = q[1], pz = q[2];
    float2 rsc = g_stats[1][b * NPTS + n];      // (COEF/Zr, 1 + S/tau)
    float A0 = rsc.x * rsc.y;                   // rsZ*c1
    float B0 = rsc.x * INV_TAU;                 // rsZ/tau
    const float4* __restrict__ cst4 = (const float4*)(g_stats[0] + b * NPTS);
    __syncthreads();

    float gx = 0.f, gy = 0.f, gz = 0.f;
#pragma unroll 2
    for (int j = 0; j < PCHUNK; j++) {
        int pi = sub + j * SUBS;
        float4 cs = __ldg(&cst4[pi]);           // (xA,yA,xB,yB)
        float4 xy = sxy4[pi];
        float2 zz = sz2[pi];
        // element A
        {
            float dx = px - xy.x, dy = py - xy.y, dz = pz - zz.x;
            float d2 = fmaxf(fmaf(dx, dx, fmaf(dy, dy, dz * dz)), 1e-12f);
            float r = rsq(d2);
            float p = ex2(d2 * r * NKEXP);
            float t1 = fmaf(cs.x, cs.y, A0);
            float t2 = fmaf(cs.x, INV_TAU, B0);
            float w = p * fmaf(t1, r, -t2);
            gx = fmaf(w, dx, gx); gy = fmaf(w, dy, gy); gz = fmaf(w, dz, gz);
        }
        // element B
        {
            float dx = px - xy.z, dy = py - xy.w, dz = pz - zz.y;
            float d2 = fmaxf(fmaf(dx, dx, fmaf(dy, dy, dz * dz)), 1e-12f);
            float r = rsq(d2);
            float p = ex2(d2 * r * NKEXP);
            float t1 = fmaf(cs.z, cs.w, A0);
            float t2 = fmaf(cs.z, INV_TAU, B0);
            float w = p * fmaf(t1, r, -t2);
            gx = fmaf(w, dx, gx); gy = fmaf(w, dy, gy); gz = fmaf(w, dz, gz);
        }
    }
    // combine SUBS lanes
#pragma unroll
    for (int o = 1; o < SUBS; o <<= 1) {
        gx += __shfl_xor_sync(0xffffffffu, gx, o);
        gy += __shfl_xor_sync(0xffffffffu, gy, o);
        gz += __shfl_xor_sync(0xffffffffu, gz, o);
    }
    if (sub == 0) {
        float nrm = sqrtf(fmaf(gx, gx, fmaf(gy, gy, gz * gz)));
        atomicAdd(&g_acc[8], fabsf(nrm - 1.f));
    }
}

// ---------------- finalize ----------------
__global__ void final_kernel(float* __restrict__ out, int bp) {
    float invBP = 1.f / (float)bp;
    float invBN = 1.f / (float)(BATCH * NPTS);
    float l1 = g_acc[0] * invBP;
    float bce = g_acc[1] * invBP;
    float unc = g_acc[2] * invBP;
    float nrm = g_acc[3] * invBP;
    float cham = (g_acc[4] + g_acc[5]) * invBN;
    float emd = (g_acc[6] + g_acc[7]) * invBN;
    float gp = g_acc[8] * invBN;
    float pt = expf(-bce);
    float occ = 0.75f * (1.f - pt) * (1.f - pt) * bce;
    out[0] = l1 + occ + 0.1f * nrm + cham + 0.25f * emd + 0.05f * gp + 0.1f * unc;
}

extern "C" void kernel_launch(void* const* d_in, const int* in_sizes, int n_in,
                              void* d_out, int out_size) {
    const float* sdf_pred   = (const float*)d_in[0];
    const float* sdf_target = (const float*)d_in[1];
    const float* uncertainty = (const float*)d_in[2];
    const float* occ_pred   = (const float*)d_in[3];
    const float* occ_target = (const float*)d_in[4];
    const float* nrm_pred   = (const float*)d_in[5];
    const float* nrm_target = (const float*)d_in[6];
    const float* pc_pred    = (const float*)d_in[7];
    const float* pc_target  = (const float*)d_in[8];
    float* out = (float*)d_out;

    int bp = in_sizes[0];   // B * P = 200000

    cudaFuncSetAttribute(stats_kernel, cudaFuncAttributeMaxDynamicSharedMemorySize,
                         (int)TILE_BYTES);
    cudaFuncSetAttribute(grad_kernel, cudaFuncAttributeMaxDynamicSharedMemorySize,
                         (int)TILE_BYTES);

    zero_kernel<<<1, 32>>>();
    pointwise_kernel<<<448, THREADS>>>(sdf_pred, sdf_target, uncertainty,
                                       occ_pred, occ_target, nrm_pred, nrm_target, bp);
    dim3 sgrid(NPTS / QPB, BATCH, 2);   // both directions in one launch
    stats_kernel<<<sgrid, THREADS, TILE_BYTES>>>(pc_pred, pc_target);
    dim3 ggrid(NPTS / QPB, BATCH);
    grad_kernel<<<ggrid, THREADS, TILE_BYTES>>>(pc_pred, pc_target);
    final_kernel<<<1, 1>>>(out, bp);
}

// round 13
// speedup vs baseline: 2.2724x; 1.2055x over previous
#include <cuda_runtime.h>
#include <math.h>

#define THREADS 256
#define NPTS 4096
#define HALF (NPTS / 2)          // 2048 opponents per tile-half
#define NPAIRS_H (HALF / 2)      // 1024 pairs
#define BATCH 2
#define BN (BATCH * NPTS)        // 8192 queries per side
#define QPB 16                   // queries per block
#define SUBS 16                  // threads per query
#define PCHUNK_H (NPAIRS_H / SUBS)   // 64 pairs per thread
#define INV_TAU 50.0f
#define NKEXP (-72.13475204444817f)  // -1/(TAU*ln2)
#define COEF (1.0f / (float)(BATCH * NPTS))

// half-tile: float4 xy-pairs [NPAIRS_H] + float2 z-pairs [NPAIRS_H] = 24KB
#define TILE_BYTES (NPAIRS_H * sizeof(float4) + NPAIRS_H * sizeof(float2))

__device__ __forceinline__ float ex2(float x) {
    float y;
    asm("ex2.approx.ftz.f32 %0, %1;" : "=f"(y) : "f"(x));
    return y;
}
__device__ __forceinline__ float rsq(float x) {
    float y;
    asm("rsqrt.approx.f32 %0, %1;" : "=f"(y) : "f"(x));
    return y;
}

// scalar accumulators: 0 l1, 1 bce, 2 unc, 3 normal, 4 chamfer_row, 5 chamfer_col,
//                      6 S-sum (EMD row), 7 T-sum (EMD col), 8 gp
__device__ float g_acc[12];
// finalized stats: [0]=col (per target m), [1]=row (per pred n); (COEF/Z, 1+T/tau)
__device__ __align__(16) float2 g_stats[2][BN];
// partial accumulators (combined across tile halves via atomics)
__device__ float g_Zp[2 * BN];
__device__ float g_Sup[2 * BN];
__device__ unsigned g_mnp[2 * BN];
__device__ float g_gp[3][BN];

__device__ __forceinline__ float warpSum(float v) {
#pragma unroll
    for (int o = 16; o > 0; o >>= 1) v += __shfl_xor_sync(0xffffffffu, v, o);
    return v;
}

__device__ __forceinline__ float blockSum(float v, float* sh) {
    __syncthreads();
    v = warpSum(v);
    int w = threadIdx.x >> 5, l = threadIdx.x & 31;
    if (l == 0) sh[w] = v;
    __syncthreads();
    if (threadIdx.x == 0) {
        float x = 0.f;
#pragma unroll
        for (int i = 0; i < THREADS / 32; i++) x += sh[i];
        sh[0] = x;
    }
    __syncthreads();
    return sh[0];
}

// ---------------- zero/init all partials ----------------
__global__ void zero_kernel() {
    int i = blockIdx.x * blockDim.x + threadIdx.x;   // 16384 threads
    if (i < 12) g_acc[i] = 0.f;
    if (i < 2 * BN) {
        g_Zp[i] = 0.f;
        g_Sup[i] = 0.f;
        g_mnp[i] = 0x7F800000u;   // +inf bits
    }
    if (i < BN) {
        g_gp[0][i] = 0.f; g_gp[1][i] = 0.f; g_gp[2][i] = 0.f;
    }
}

// ---------------- pointwise losses over B*P points ----------------
__global__ void pointwise_kernel(const float* __restrict__ sp, const float* __restrict__ st,
                                 const float* __restrict__ un, const float* __restrict__ op,
                                 const float* __restrict__ ot, const float* __restrict__ na_,
                                 const float* __restrict__ nb_, int n) {
    float s_l1 = 0.f, s_bce = 0.f, s_unc = 0.f, s_nrm = 0.f;
    for (int i = blockIdx.x * blockDim.x + threadIdx.x; i < n; i += gridDim.x * blockDim.x) {
        s_l1 += fabsf(sp[i] - st[i]);
        float p = op[i], t = ot[i];
        s_bce -= t * __logf(p) + (1.f - t) * __logf(1.f - p);
        float u = un[i];
        s_unc += u * (1.f - u);
        float ax = na_[3 * i], ay = na_[3 * i + 1], az = na_[3 * i + 2];
        float bx = nb_[3 * i], by = nb_[3 * i + 1], bz = nb_[3 * i + 2];
        float nna2 = fmaf(ax, ax, fmaf(ay, ay, az * az));
        float nnb2 = fmaf(bx, bx, fmaf(by, by, bz * bz));
        float inv = rsq(fmaxf(nna2, 1e-16f)) * rsq(fmaxf(nnb2, 1e-16f));
        float cs = fmaf(ax, bx, fmaf(ay, by, az * bz)) * inv;
        s_nrm += 1.f - cs;
    }
    __shared__ float sh[8];
    float v;
    v = blockSum(s_l1, sh);  if (threadIdx.x == 0) atomicAdd(&g_acc[0], v);
    v = blockSum(s_bce, sh); if (threadIdx.x == 0) atomicAdd(&g_acc[1], v);
    v = blockSum(s_unc, sh); if (threadIdx.x == 0) atomicAdd(&g_acc[2], v);
    v = blockSum(s_nrm, sh); if (threadIdx.x == 0) atomicAdd(&g_acc[3], v);
}

// pack a 2048-point half into pair planes: float4(x0,y0,x1,y1), float2(z0,z1)
__device__ __forceinline__ void fill_pairs(float4* sxy4, float2* sz2,
                                           const float* __restrict__ base, int t) {
#pragma unroll
    for (int j = 0; j < NPAIRS_H / THREADS; j++) {   // 4
        int p = t + j * THREADS;
        const float* s = base + 6 * p;
        sxy4[p] = make_float4(s[0], s[1], s[3], s[4]);
        sz2[p] = make_float2(s[2], s[5]);
    }
}

// -------- stats: partial softmax stats per query over one opponent half --------
// blockIdx.z: bit1 = side (0: queries=targets/opp=preds, 1: queries=preds/opp=targets)
//             bit0 = tile half
__global__ void stats_kernel(const float* __restrict__ prd, const float* __restrict__ tgt) {
    extern __shared__ float sm[];
    float4* sxy4 = (float4*)sm;
    float2* sz2 = (float2*)(sm + 4 * NPAIRS_H);
    int t = threadIdx.x;
    int b = blockIdx.y;
    int side = blockIdx.z >> 1, half = blockIdx.z & 1;
    const float* qbase = side == 0 ? tgt : prd;
    const float* obase = side == 0 ? prd : tgt;
    int qloc = t / SUBS, sub = t % SUBS;
    int m = blockIdx.x * QPB + qloc;

    fill_pairs(sxy4, sz2, obase + (size_t)b * NPTS * 3 + (size_t)half * HALF * 3, t);
    const float* q = qbase + ((size_t)b * NPTS + m) * 3;
    float px = q[0], py = q[1], pz = q[2];
    __syncthreads();

    float mn2 = 1e30f, Z = 0.f, Su = 0.f;
#pragma unroll 4
    for (int j = 0; j < PCHUNK_H; j++) {
        int pi = sub + j * SUBS;
        float4 xy = sxy4[pi];
        float2 zz = sz2[pi];
        {
            float dx = px - xy.x, dy = py - xy.y, dz = pz - zz.x;
            float d2 = fmaxf(fmaf(dx, dx, fmaf(dy, dy, dz * dz)), 1e-12f);
            mn2 = fminf(mn2, d2);
            float r = rsq(d2);
            float d = d2 * r;
            float p = ex2(d * NKEXP);
            Z += p;
            Su = fmaf(p, d, Su);
        }
        {
            float dx = px - xy.z, dy = py - xy.w, dz = pz - zz.y;
            float d2 = fmaxf(fmaf(dx, dx, fmaf(dy, dy, dz * dz)), 1e-12f);
            mn2 = fminf(mn2, d2);
            float r = rsq(d2);
            float d = d2 * r;
            float p = ex2(d * NKEXP);
            Z += p;
            Su = fmaf(p, d, Su);
        }
    }
#pragma unroll
    for (int o = 1; o < SUBS; o <<= 1) {
        mn2 = fminf(mn2, __shfl_xor_sync(0xffffffffu, mn2, o));
        Z += __shfl_xor_sync(0xffffffffu, Z, o);
        Su += __shfl_xor_sync(0xffffffffu, Su, o);
    }
    if (sub == 0) {
        int idx = side * BN + b * NPTS + m;
        atomicAdd(&g_Zp[idx], Z);
        atomicAdd(&g_Sup[idx], Su);
        atomicMin(&g_mnp[idx], __float_as_uint(mn2));
    }
}

// -------- finalize stats: 16384 queries (side-major so warps are side-uniform) --------
__global__ void stats_fin_kernel() {
    int i = blockIdx.x * blockDim.x + threadIdx.x;   // 0..16383
    int side = i >> 13;
    int q = i & (BN - 1);
    float Z = g_Zp[i];
    float T = g_Sup[i] / Z;
    g_stats[side][q] = make_float2(COEF / Z, fmaf(T, INV_TAU, 1.f));
    float mn = sqrtf(__uint_as_float(g_mnp[i]));
    float mnS = warpSum(mn);
    float TS = warpSum(T);
    if ((threadIdx.x & 31) == 0) {
        atomicAdd(&g_acc[5 - side], mnS);   // chamfer
        atomicAdd(&g_acc[7 - side], TS);    // EMD term
    }
}

// -------- grad: EMD gradient partials over one target half --------
__global__ void grad_kernel(const float* __restrict__ prd, const float* __restrict__ tgt) {
    extern __shared__ float sm[];
    float4* sxy4 = (float4*)sm;
    float2* sz2 = (float2*)(sm + 4 * NPAIRS_H);
    int t = threadIdx.x;
    int b = blockIdx.y;
    int half = blockIdx.z;
    int qloc = t / SUBS, sub = t % SUBS;
    int n = blockIdx.x * QPB + qloc;

    fill_pairs(sxy4, sz2, tgt + (size_t)b * NPTS * 3 + (size_t)half * HALF * 3, t);
    const float* q = prd + ((size_t)b * NPTS + n) * 3;
    float px = q[0], py = q[1], pz = q[2];
    float2 rsc = g_stats[1][b * NPTS + n];      // (COEF/Zr, 1 + S/tau)
    float A0 = rsc.x * rsc.y;
    float B0 = rsc.x * INV_TAU;
    const float4* __restrict__ cst4 = (const float4*)(g_stats[0] + b * NPTS + half * HALF);
    __syncthreads();

    float gx = 0.f, gy = 0.f, gz = 0.f;
#pragma unroll 4
    for (int j = 0; j < PCHUNK_H; j++) {
        int pi = sub + j * SUBS;
        float4 cs = __ldg(&cst4[pi]);           // (xA,yA,xB,yB)
        float4 xy = sxy4[pi];
        float2 zz = sz2[pi];
        {
            float dx = px - xy.x, dy = py - xy.y, dz = pz - zz.x;
            float d2 = fmaxf(fmaf(dx, dx, fmaf(dy, dy, dz * dz)), 1e-12f);
            float r = rsq(d2);
            float p = ex2(d2 * r * NKEXP);
            float t1 = fmaf(cs.x, cs.y, A0);
            float t2 = fmaf(cs.x, INV_TAU, B0);
            float w = p * fmaf(t1, r, -t2);
            gx = fmaf(w, dx, gx); gy = fmaf(w, dy, gy); gz = fmaf(w, dz, gz);
        }
        {
            float dx = px - xy.z, dy = py - xy.w, dz = pz - zz.y;
            float d2 = fmaxf(fmaf(dx, dx, fmaf(dy, dy, dz * dz)), 1e-12f);
            float r = rsq(d2);
            float p = ex2(d2 * r * NKEXP);
            float t1 = fmaf(cs.z, cs.w, A0);
            float t2 = fmaf(cs.z, INV_TAU, B0);
            float w = p * fmaf(t1, r, -t2);
            gx = fmaf(w, dx, gx); gy = fmaf(w, dy, gy); gz = fmaf(w, dz, gz);
        }
    }
#pragma unroll
    for (int o = 1; o < SUBS; o <<= 1) {
        gx += __shfl_xor_sync(0xffffffffu, gx, o);
        gy += __shfl_xor_sync(0xffffffffu, gy, o);
        gz += __shfl_xor_sync(0xffffffffu, gz, o);
    }
    if (sub == 0) {
        int idx = b * NPTS + n;
        atomicAdd(&g_gp[0][idx], gx);
        atomicAdd(&g_gp[1][idx], gy);
        atomicAdd(&g_gp[2][idx], gz);
    }
}

// -------- finalize grad: 8192 queries --------
__global__ void grad_fin_kernel() {
    int i = blockIdx.x * blockDim.x + threadIdx.x;   // 0..8191
    float gx = g_gp[0][i], gy = g_gp[1][i], gz = g_gp[2][i];
    float nrm = sqrtf(fmaf(gx, gx, fmaf(gy, gy, gz * gz)));
    float v = fabsf(nrm - 1.f);
    float vs = warpSum(v);
    if ((threadIdx.x & 31) == 0) atomicAdd(&g_acc[8], vs);
}

// ---------------- finalize ----------------
__global__ void final_kernel(float* __restrict__ out, int bp) {
    float invBP = 1.f / (float)bp;
    float invBN = 1.f / (float)BN;
    float l1 = g_acc[0] * invBP;
    float bce = g_acc[1] * invBP;
    float unc = g_acc[2] * invBP;
    float nrm = g_acc[3] * invBP;
    float cham = (g_acc[4] + g_acc[5]) * invBN;
    float emd = (g_acc[6] + g_acc[7]) * invBN;
    float gp = g_acc[8] * invBN;
    float pt = expf(-bce);
    float occ = 0.75f * (1.f - pt) * (1.f - pt) * bce;
    out[0] = l1 + occ + 0.1f * nrm + cham + 0.25f * emd + 0.05f * gp + 0.1f * unc;
}

extern "C" void kernel_launch(void* const* d_in, const int* in_sizes, int n_in,
                              void* d_out, int out_size) {
    const float* sdf_pred   = (const float*)d_in[0];
    const float* sdf_target = (const float*)d_in[1];
    const float* uncertainty = (const float*)d_in[2];
    const float* occ_pred   = (const float*)d_in[3];
    const float* occ_target = (const float*)d_in[4];
    const float* nrm_pred   = (const float*)d_in[5];
    const float* nrm_target = (const float*)d_in[6];
    const float* pc_pred    = (const float*)d_in[7];
    const float* pc_target  = (const float*)d_in[8];
    float* out = (float*)d_out;

    int bp = in_sizes[0];   // B * P = 200000

    zero_kernel<<<64, THREADS>>>();
    pointwise_kernel<<<448, THREADS>>>(sdf_pred, sdf_target, uncertainty,
                                       occ_pred, occ_target, nrm_pred, nrm_target, bp);
    dim3 sgrid(NPTS / QPB, BATCH, 4);   // 2 sides x 2 halves
    stats_kernel<<<sgrid, THREADS, TILE_BYTES>>>(pc_pred, pc_target);
    stats_fin_kernel<<<64, THREADS>>>();
    dim3 ggrid(NPTS / QPB, BATCH, 2);   // 2 halves
    grad_kernel<<<ggrid, THREADS, TILE_BYTES>>>(pc_pred, pc_target);
    grad_fin_kernel<<<32, THREADS>>>();
    final_kernel<<<1, 1>>>(out, bp);
}

// round 14
// speedup vs baseline: 2.5423x; 1.1188x over previous
#include <cuda_runtime.h>
#include <math.h>

#define THREADS 256
#define NPTS 4096
#define HALF (NPTS / 2)          // 2048 opponents per tile-half
#define NPAIRS_H (HALF / 2)      // 1024 pairs
#define BATCH 2
#define BN (BATCH * NPTS)        // 8192 queries per side
#define QPB 16                   // queries per block
#define SUBS 16                  // threads per query
#define PCHUNK_H (NPAIRS_H / SUBS)   // 64 pairs per thread
#define INV_TAU 50.0f
#define NKEXP (-72.13475204444817f)  // -1/(TAU*ln2)
#define INV_NK (-0.013862943611198906f)   // 1/NKEXP = -TAU*ln2
#define COEF (1.0f / (float)(BATCH * NPTS))
#define PW_BLOCKS 448

// half-tile: float4 xy-pairs [NPAIRS_H] + float2 z-pairs [NPAIRS_H] = 24KB
#define TILE_BYTES (NPAIRS_H * sizeof(float4) + NPAIRS_H * sizeof(float2))

__device__ __forceinline__ float ex2(float x) {
    float y;
    asm("ex2.approx.ftz.f32 %0, %1;" : "=f"(y) : "f"(x));
    return y;
}
__device__ __forceinline__ float rsq(float x) {
    float y;
    asm("rsqrt.approx.f32 %0, %1;" : "=f"(y) : "f"(x));
    return y;
}
__device__ __forceinline__ float sqa(float x) {
    float y;
    asm("sqrt.approx.ftz.f32 %0, %1;" : "=f"(y) : "f"(x));
    return y;
}
__device__ __forceinline__ float rcp(float x) {
    float y;
    asm("rcp.approx.ftz.f32 %0, %1;" : "=f"(y) : "f"(x));
    return y;
}

// ---- partials: every slot written unconditionally each run (no init, no atomics) ----
__device__ float g_pw[4][PW_BLOCKS];                // pointwise block sums
__device__ float g_Zp[2][2][BN];                    // [side][half][query]
__device__ float g_Sup[2][2][BN];                   // scaled: sum p*(d*NKEXP)
__device__ float g_mnp[2][2][BN];                   // min d2
__device__ __align__(16) float2 g_stats[2][BN];     // (COEF/Z, 1+T/tau)
__device__ float g_sf_mn[64];                       // stats_fin block sums (chamfer)
__device__ float g_sf_T[64];                        // stats_fin block sums (EMD)
__device__ float g_gp[2][3][BN];                    // grad partials per half
__device__ float g_gf[32];                          // grad_fin block sums

__device__ __forceinline__ float warpSum(float v) {
#pragma unroll
    for (int o = 16; o > 0; o >>= 1) v += __shfl_xor_sync(0xffffffffu, v, o);
    return v;
}

__device__ __forceinline__ float blockSum(float v, float* sh) {
    __syncthreads();
    v = warpSum(v);
    int w = threadIdx.x >> 5, l = threadIdx.x & 31;
    if (l == 0) sh[w] = v;
    __syncthreads();
    if (threadIdx.x == 0) {
        float x = 0.f;
#pragma unroll
        for (int i = 0; i < THREADS / 32; i++) x += sh[i];
        sh[0] = x;
    }
    __syncthreads();
    return sh[0];
}

// ---------------- pointwise losses over B*P points ----------------
__global__ void pointwise_kernel(const float* __restrict__ sp, const float* __restrict__ st,
                                 const float* __restrict__ un, const float* __restrict__ op,
                                 const float* __restrict__ ot, const float* __restrict__ na_,
                                 const float* __restrict__ nb_, int n) {
    float s_l1 = 0.f, s_bce = 0.f, s_unc = 0.f, s_nrm = 0.f;
    for (int i = blockIdx.x * blockDim.x + threadIdx.x; i < n; i += gridDim.x * blockDim.x) {
        s_l1 += fabsf(sp[i] - st[i]);
        float p = op[i], t = ot[i];
        s_bce -= t * __logf(p) + (1.f - t) * __logf(1.f - p);
        float u = un[i];
        s_unc += u * (1.f - u);
        float ax = na_[3 * i], ay = na_[3 * i + 1], az = na_[3 * i + 2];
        float bx = nb_[3 * i], by = nb_[3 * i + 1], bz = nb_[3 * i + 2];
        float nna2 = fmaf(ax, ax, fmaf(ay, ay, az * az));
        float nnb2 = fmaf(bx, bx, fmaf(by, by, bz * bz));
        float inv = rsq(fmaxf(nna2, 1e-16f)) * rsq(fmaxf(nnb2, 1e-16f));
        float cs = fmaf(ax, bx, fmaf(ay, by, az * bz)) * inv;
        s_nrm += 1.f - cs;
    }
    __shared__ float sh[8];
    float v;
    v = blockSum(s_l1, sh);  if (threadIdx.x == 0) g_pw[0][blockIdx.x] = v;
    v = blockSum(s_bce, sh); if (threadIdx.x == 0) g_pw[1][blockIdx.x] = v;
    v = blockSum(s_unc, sh); if (threadIdx.x == 0) g_pw[2][blockIdx.x] = v;
    v = blockSum(s_nrm, sh); if (threadIdx.x == 0) g_pw[3][blockIdx.x] = v;
}

// pack a 2048-point half into pair planes: float4(x0,y0,x1,y1), float2(z0,z1)
__device__ __forceinline__ void fill_pairs(float4* sxy4, float2* sz2,
                                           const float* __restrict__ base, int t) {
#pragma unroll
    for (int j = 0; j < NPAIRS_H / THREADS; j++) {   // 4
        int p = t + j * THREADS;
        const float* s = base + 6 * p;
        sxy4[p] = make_float4(s[0], s[1], s[3], s[4]);
        sz2[p] = make_float2(s[2], s[5]);
    }
}

// -------- stats: partial softmax stats per query over one opponent half --------
// blockIdx.z: bit1 = side, bit0 = tile half
__global__ void stats_kernel(const float* __restrict__ prd, const float* __restrict__ tgt) {
    extern __shared__ float sm[];
    float4* sxy4 = (float4*)sm;
    float2* sz2 = (float2*)(sm + 4 * NPAIRS_H);
    int t = threadIdx.x;
    int b = blockIdx.y;
    int side = blockIdx.z >> 1, half = blockIdx.z & 1;
    const float* qbase = side == 0 ? tgt : prd;
    const float* obase = side == 0 ? prd : tgt;
    int qloc = t / SUBS, sub = t % SUBS;
    int m = blockIdx.x * QPB + qloc;

    fill_pairs(sxy4, sz2, obase + (size_t)b * NPTS * 3 + (size_t)half * HALF * 3, t);
    const float* q = qbase + ((size_t)b * NPTS + m) * 3;
    float px = q[0], py = q[1], pz = q[2];
    __syncthreads();

    float mn2 = 1e30f, Z = 0.f, Su = 0.f;   // Su accumulates p*(d*NKEXP)
#pragma unroll 4
    for (int j = 0; j < PCHUNK_H; j++) {
        int pi = sub + j * SUBS;
        float4 xy = sxy4[pi];
        float2 zz = sz2[pi];
        {
            float dx = px - xy.x, dy = py - xy.y, dz = pz - zz.x;
            float d2 = fmaxf(fmaf(dx, dx, fmaf(dy, dy, dz * dz)), 1e-12f);
            mn2 = fminf(mn2, d2);
            float arg = sqa(d2) * NKEXP;
            float p = ex2(arg);
            Z += p;
            Su = fmaf(p, arg, Su);
        }
        {
            float dx = px - xy.z, dy = py - xy.w, dz = pz - zz.y;
            float d2 = fmaxf(fmaf(dx, dx, fmaf(dy, dy, dz * dz)), 1e-12f);
            mn2 = fminf(mn2, d2);
            float arg = sqa(d2) * NKEXP;
            float p = ex2(arg);
            Z += p;
            Su = fmaf(p, arg, Su);
        }
    }
#pragma unroll
    for (int o = 1; o < SUBS; o <<= 1) {
        mn2 = fminf(mn2, __shfl_xor_sync(0xffffffffu, mn2, o));
        Z += __shfl_xor_sync(0xffffffffu, Z, o);
        Su += __shfl_xor_sync(0xffffffffu, Su, o);
    }
    if (sub == 0) {
        int idx = b * NPTS + m;
        g_Zp[side][half][idx] = Z;
        g_Sup[side][half][idx] = Su;
        g_mnp[side][half][idx] = mn2;
    }
}

// -------- finalize stats: 16384 queries --------
__global__ void stats_fin_kernel() {
    int i = blockIdx.x * blockDim.x + threadIdx.x;   // 0..16383
    int side = i >> 13;
    int q = i & (BN - 1);
    float Z = g_Zp[side][0][q] + g_Zp[side][1][q];
    float Su = g_Sup[side][0][q] + g_Sup[side][1][q];
    float rz = rcp(Z);
    float T = Su * rz * INV_NK;
    g_stats[side][q] = make_float2(COEF * rz, fmaf(T, INV_TAU, 1.f));
    float mn = sqrtf(fminf(g_mnp[side][0][q], g_mnp[side][1][q]));
    __shared__ float sh[8];
    float mnS = blockSum(mn, sh);
    float TS = blockSum(T, sh);
    if (threadIdx.x == 0) {
        g_sf_mn[blockIdx.x] = mnS;
        g_sf_T[blockIdx.x] = TS;
    }
}

// -------- grad: EMD gradient partials over one target half --------
__global__ void grad_kernel(const float* __restrict__ prd, const float* __restrict__ tgt) {
    extern __shared__ float sm[];
    float4* sxy4 = (float4*)sm;
    float2* sz2 = (float2*)(sm + 4 * NPAIRS_H);
    int t = threadIdx.x;
    int b = blockIdx.y;
    int half = blockIdx.z;
    int qloc = t / SUBS, sub = t % SUBS;
    int n = blockIdx.x * QPB + qloc;

    fill_pairs(sxy4, sz2, tgt + (size_t)b * NPTS * 3 + (size_t)half * HALF * 3, t);
    const float* q = prd + ((size_t)b * NPTS + n) * 3;
    float px = q[0], py = q[1], pz = q[2];
    float2 rsc = g_stats[1][b * NPTS + n];      // (COEF/Zr, 1 + S/tau)
    float A0 = rsc.x * rsc.y;
    float B0 = rsc.x * INV_TAU;
    const float4* __restrict__ cst4 = (const float4*)(g_stats[0] + b * NPTS + half * HALF);
    __syncthreads();

    float gx = 0.f, gy = 0.f, gz = 0.f;
#pragma unroll 4
    for (int j = 0; j < PCHUNK_H; j++) {
        int pi = sub + j * SUBS;
        float4 cs = __ldg(&cst4[pi]);           // (xA,yA,xB,yB)
        float4 xy = sxy4[pi];
        float2 zz = sz2[pi];
        {
            float dx = px - xy.x, dy = py - xy.y, dz = pz - zz.x;
            float d2 = fmaxf(fmaf(dx, dx, fmaf(dy, dy, dz * dz)), 1e-12f);
            float r = rsq(d2);
            float p = ex2(d2 * r * NKEXP);
            float t1 = fmaf(cs.x, cs.y, A0);
            float t2 = fmaf(cs.x, INV_TAU, B0);
            float w = p * fmaf(t1, r, -t2);
            gx = fmaf(w, dx, gx); gy = fmaf(w, dy, gy); gz = fmaf(w, dz, gz);
        }
        {
            float dx = px - xy.z, dy = py - xy.w, dz = pz - zz.y;
            float d2 = fmaxf(fmaf(dx, dx, fmaf(dy, dy, dz * dz)), 1e-12f);
            float r = rsq(d2);
            float p = ex2(d2 * r * NKEXP);
            float t1 = fmaf(cs.z, cs.w, A0);
            float t2 = fmaf(cs.z, INV_TAU, B0);
            float w = p * fmaf(t1, r, -t2);
            gx = fmaf(w, dx, gx); gy = fmaf(w, dy, gy); gz = fmaf(w, dz, gz);
        }
    }
#pragma unroll
    for (int o = 1; o < SUBS; o <<= 1) {
        gx += __shfl_xor_sync(0xffffffffu, gx, o);
        gy += __shfl_xor_sync(0xffffffffu, gy, o);
        gz += __shfl_xor_sync(0xffffffffu, gz, o);
    }
    if (sub == 0) {
        int idx = b * NPTS + n;
        g_gp[half][0][idx] = gx;
        g_gp[half][1][idx] = gy;
        g_gp[half][2][idx] = gz;
    }
}

// -------- finalize grad: 8192 queries --------
__global__ void grad_fin_kernel() {
    int i = blockIdx.x * blockDim.x + threadIdx.x;   // 0..8191
    float gx = g_gp[0][0][i] + g_gp[1][0][i];
    float gy = g_gp[0][1][i] + g_gp[1][1][i];
    float gz = g_gp[0][2][i] + g_gp[1][2][i];
    float nrm = sqrtf(fmaf(gx, gx, fmaf(gy, gy, gz * gz)));
    __shared__ float sh[8];
    float vs = blockSum(fabsf(nrm - 1.f), sh);
    if (threadIdx.x == 0) g_gf[blockIdx.x] = vs;
}

// ---------------- final: gather all partials, compute total ----------------
__global__ void final_kernel(float* __restrict__ out, int bp) {
    int t = threadIdx.x;
    float s0 = 0.f, s1 = 0.f, s2 = 0.f, s3 = 0.f, sMn = 0.f, sT = 0.f, sG = 0.f;
    for (int i = t; i < PW_BLOCKS; i += THREADS) {
        s0 += g_pw[0][i]; s1 += g_pw[1][i]; s2 += g_pw[2][i]; s3 += g_pw[3][i];
    }
    if (t < 64) { sMn = g_sf_mn[t]; sT = g_sf_T[t]; }
    if (t < 32) sG = g_gf[t];
    __shared__ float sh[8];
    s0 = blockSum(s0, sh);
    s1 = blockSum(s1, sh);
    s2 = blockSum(s2, sh);
    s3 = blockSum(s3, sh);
    sMn = blockSum(sMn, sh);
    sT = blockSum(sT, sh);
    sG = blockSum(sG, sh);
    if (t == 0) {
        float invBP = 1.f / (float)bp;
        float invBN = 1.f / (float)BN;
        float l1 = s0 * invBP;
        float bce = s1 * invBP;
        float unc = s2 * invBP;
        float nrm = s3 * invBP;
        float cham = sMn * invBN;
        float emd = sT * invBN;
        float gp = sG * invBN;
        float pt = expf(-bce);
        float occ = 0.75f * (1.f - pt) * (1.f - pt) * bce;
        out[0] = l1 + occ + 0.1f * nrm + cham + 0.25f * emd + 0.05f * gp + 0.1f * unc;
    }
}

extern "C" void kernel_launch(void* const* d_in, const int* in_sizes, int n_in,
                              void* d_out, int out_size) {
    const float* sdf_pred   = (const float*)d_in[0];
    const float* sdf_target = (const float*)d_in[1];
    const float* uncertainty = (const float*)d_in[2];
    const float* occ_pred   = (const float*)d_in[3];
    const float* occ_target = (const float*)d_in[4];
    const float* nrm_pred   = (const float*)d_in[5];
    const float* nrm_target = (const float*)d_in[6];
    const float* pc_pred    = (const float*)d_in[7];
    const float* pc_target  = (const float*)d_in[8];
    float* out = (float*)d_out;

    int bp = in_sizes[0];   // B * P = 200000

    pointwise_kernel<<<PW_BLOCKS, THREADS>>>(sdf_pred, sdf_target, uncertainty,
                                             occ_pred, occ_target, nrm_pred, nrm_target, bp);
    dim3 sgrid(NPTS / QPB, BATCH, 4);   // 2 sides x 2 halves
    stats_kernel<<<sgrid, THREADS, TILE_BYTES>>>(pc_pred, pc_target);
    stats_fin_kernel<<<64, THREADS>>>();
    dim3 ggrid(NPTS / QPB, BATCH, 2);   // 2 halves
    grad_kernel<<<ggrid, THREADS, TILE_BYTES>>>(pc_pred, pc_target);
    grad_fin_kernel<<<32, THREADS>>>();
    final_kernel<<<1, THREADS>>>(out, bp);
}